// round 13
// baseline (speedup 1.0000x reference)
#include <cuda_runtime.h>
#include <cstdint>

// Problem constants
#define B_ 16
#define L_ 680
#define C_ 1024
#define H_ 16
#define D_ 64
#define M_ (B_ * L_)     // 10880
#define N1_ (3 * C_)     // 3072
#define MAXLOG 4.605170185988091f   // ln(100)

// ---------------- scratch (static __device__, no allocations) ----------------
__device__ float g_qkv[(size_t)M_ * N1_];          // GEMM1 output [M, 3C]
__device__ float g_q[(size_t)B_ * H_ * L_ * D_];   // normalized q, [B,H,L,D]
__device__ float g_k[(size_t)B_ * H_ * L_ * D_];
__device__ float g_v[(size_t)B_ * H_ * L_ * D_];
__device__ float g_att[(size_t)M_ * C_];           // attention out (tf32-rounded)
__device__ float g_xr[(size_t)M_ * C_];            // x rounded to tf32
__device__ float g_wqkvr[(size_t)N1_ * C_];        // wqkv rounded to tf32
__device__ float g_wpr[(size_t)C_ * C_];           // wp rounded to tf32

// ---------------- helpers ----------------
__device__ __forceinline__ unsigned f2tf(float x) {
    unsigned r;
    asm("cvt.rna.tf32.f32 %0, %1;" : "=r"(r) : "f"(x));
    return r;
}

__device__ __forceinline__ void mma_tf32(float c[4], const unsigned a[4],
                                         unsigned b0, unsigned b1) {
    asm volatile(
        "mma.sync.aligned.m16n8k8.row.col.f32.tf32.tf32.f32 "
        "{%0,%1,%2,%3}, {%4,%5,%6,%7}, {%8,%9}, {%0,%1,%2,%3};"
        : "+f"(c[0]), "+f"(c[1]), "+f"(c[2]), "+f"(c[3])
        : "r"(a[0]), "r"(a[1]), "r"(a[2]), "r"(a[3]), "r"(b0), "r"(b1));
}

__device__ __forceinline__ void cp16(unsigned* s, const float* g) {
    unsigned sa = (unsigned)__cvta_generic_to_shared(s);
    asm volatile("cp.async.cg.shared.global [%0], [%1], 16;" :: "r"(sa), "l"(g));
}
__device__ __forceinline__ void cp_commit() {
    asm volatile("cp.async.commit_group;");
}
template<int N> __device__ __forceinline__ void cp_wait() {
    asm volatile("cp.async.wait_group %0;" :: "n"(N));
}

// packed f32x2 primitives — operands STAY packed (no movs in hot loops)
typedef unsigned long long u64;
__device__ __forceinline__ void pfma(u64& d, u64 a, u64 b) {
    asm("fma.rn.f32x2 %0, %1, %2, %0;" : "+l"(d) : "l"(a), "l"(b));
}
__device__ __forceinline__ float2 up2(u64 v) {
    float2 r; asm("mov.b64 {%0, %1}, %2;" : "=f"(r.x), "=f"(r.y) : "l"(v)); return r;
}
__device__ __forceinline__ u64 pk2(float x, float y) {
    u64 r; asm("mov.b64 %0, {%1, %2};" : "=l"(r) : "f"(x), "f"(y)); return r;
}

// ---------------- tf32 pre-round (elementwise) ----------------
__global__ __launch_bounds__(256)
void round_tf32_kernel(const float* __restrict__ src, float* __restrict__ dst, int n)
{
    int i = (blockIdx.x * 256 + threadIdx.x) * 4;
    if (i < n) {
        float4 v = *(const float4*)(src + i);
        uint4 r = make_uint4(f2tf(v.x), f2tf(v.y), f2tf(v.z), f2tf(v.w));
        *(uint4*)(dst + i) = r;
    }
}

// ---------------- GEMM: C[m,n] = sum_k A[m,k]*W[n,k] + bias(n) ----------------
// Pre-rounded tf32 inputs; no cvt in hot loop. 256 threads (8 warps),
// CTA tile 128x128, warp tile 64x32. 3-stage cp.async pipeline with ONE
// __syncthreads per k-chunk (stage refilled at iter it was consumed at it-1,
// so the top barrier already orders the WAR). 110.6 KB smem -> 2 CTAs/SM.
// mode 0: bias = b0p[n]   (proj)
// mode 1: qkv bias: n<1024 -> b0p[n]; n<2048 -> 0; else b1p[n-2048]
#define SROW 36                       // +4 pad: fragment LDS conflict-free
#define STAGEF (2 * 128 * SROW)       // words per stage (A then B)
#define GEMM_SMEM (3 * STAGEF * 4)    // 110592 B

__global__ __launch_bounds__(256, 2)
void gemm_tf32_kernel(const float* __restrict__ A, const float* __restrict__ W,
                      const float* __restrict__ b0p, const float* __restrict__ b1p,
                      float* __restrict__ Cout, int N, int K, int mode)
{
    extern __shared__ unsigned sm[];

    const int bm = blockIdx.y * 128, bn = blockIdx.x * 128;
    const int tid  = threadIdx.x;
    const int lane = tid & 31, warp = tid >> 5;
    const int wm = (warp & 1) * 64;    // 2 warps along m
    const int wn = (warp >> 1) * 32;   // 4 warps along n
    const int gid = lane >> 2, tig = lane & 3;
    const int lrow = tid >> 3;         // 0..31
    const int lcol = (tid & 7) * 4;    // 0,4,...,28

    float acc[4][4][4];
    #pragma unroll
    for (int mt = 0; mt < 4; mt++)
        #pragma unroll
        for (int nt = 0; nt < 4; nt++)
            #pragma unroll
            for (int r = 0; r < 4; r++) acc[mt][nt][r] = 0.f;

    const float* Ag = A + (size_t)(bm + lrow) * K + lcol;
    const float* Wg = W + (size_t)(bn + lrow) * K + lcol;

    const int NCH = K >> 5;            // 32-wide k chunks

    auto load_chunk = [&](int c, int s) {
        unsigned* sA = sm + s * STAGEF;
        unsigned* sB = sA + 128 * SROW;
        const float* Ap = Ag + (size_t)c * 32;
        const float* Wp = Wg + (size_t)c * 32;
        #pragma unroll
        for (int i = 0; i < 4; i++) {
            cp16(&sA[(lrow + i * 32) * SROW + lcol], Ap + (size_t)i * 32 * K);
            cp16(&sB[(lrow + i * 32) * SROW + lcol], Wp + (size_t)i * 32 * K);
        }
        cp_commit();
    };

    // prologue: stage 0 <- chunk 0, stage 1 <- chunk 1
    load_chunk(0, 0);
    load_chunk(1, 1);

    int scur = 0;                      // stage of chunk `it`
    for (int it = 0; it < NCH; it++) {
        if (it < NCH - 1) cp_wait<1>(); else cp_wait<0>();
        __syncthreads();               // chunk `it` visible; chunk `it-1` fully read

        if (it + 2 < NCH) {
            int snx = scur + 2; if (snx >= 3) snx -= 3;
            load_chunk(it + 2, snx);   // refills the stage consumed at it-1
        }

        const unsigned* sA = sm + scur * STAGEF;
        const unsigned* sB = sA + 128 * SROW;

        #pragma unroll
        for (int ks = 0; ks < 32; ks += 8) {
            unsigned a[4][4];
            #pragma unroll
            for (int mt = 0; mt < 4; mt++) {
                int r = wm + mt * 16 + gid;
                a[mt][0] = sA[r * SROW + ks + tig];
                a[mt][1] = sA[(r + 8) * SROW + ks + tig];
                a[mt][2] = sA[r * SROW + ks + tig + 4];
                a[mt][3] = sA[(r + 8) * SROW + ks + tig + 4];
            }
            #pragma unroll
            for (int nt = 0; nt < 4; nt++) {
                int n = wn + nt * 8 + gid;
                unsigned bb0 = sB[n * SROW + ks + tig];
                unsigned bb1 = sB[n * SROW + ks + tig + 4];
                #pragma unroll
                for (int mt = 0; mt < 4; mt++)
                    mma_tf32(acc[mt][nt], a[mt], bb0, bb1);
            }
        }
        scur = scur + 1; if (scur >= 3) scur = 0;
    }

    #pragma unroll
    for (int mt = 0; mt < 4; mt++) {
        #pragma unroll
        for (int nt = 0; nt < 4; nt++) {
            int row = bm + wm + mt * 16 + gid;
            int col = bn + wn + nt * 8 + 2 * tig;
            float bz0, bz1;
            if (mode == 0) {
                bz0 = b0p[col]; bz1 = b0p[col + 1];
            } else {
                if (col < 1024)       { bz0 = b0p[col];        bz1 = b0p[col + 1]; }
                else if (col < 2048)  { bz0 = 0.f;             bz1 = 0.f; }
                else                  { bz0 = b1p[col - 2048]; bz1 = b1p[col - 2047]; }
            }
            *(float2*)&Cout[(size_t)row * N + col] =
                make_float2(acc[mt][nt][0] + bz0, acc[mt][nt][1] + bz1);
            *(float2*)&Cout[(size_t)(row + 8) * N + col] =
                make_float2(acc[mt][nt][2] + bz0, acc[mt][nt][3] + bz1);
        }
    }
}

// ---------------- l2norm + scale + transpose to [B,H,L,D] ----------------
__global__ __launch_bounds__(256)
void norm_kernel(const float* __restrict__ Y, const float* __restrict__ sl,
                 float* __restrict__ Q, float* __restrict__ Ko, float* __restrict__ V)
{
    int w    = blockIdx.x * 8 + (threadIdx.x >> 5);   // one warp per (m,h)
    int lane = threadIdx.x & 31;
    int m = w >> 4, h = w & 15;
    int b = m / L_, l = m % L_;

    const float* row = Y + (size_t)m * N1_ + h * 64 + lane * 2;
    float2 qv = *(const float2*)(row);
    float2 kv = *(const float2*)(row + 1024);
    float2 vv = *(const float2*)(row + 2048);

    float ssq = qv.x * qv.x + qv.y * qv.y;
    float ssk = kv.x * kv.x + kv.y * kv.y;
    #pragma unroll
    for (int o = 16; o; o >>= 1) {
        ssq += __shfl_xor_sync(0xffffffffu, ssq, o);
        ssk += __shfl_xor_sync(0xffffffffu, ssk, o);
    }
    float qs = expf(fminf(sl[h], MAXLOG)) / fmaxf(sqrtf(ssq), 1e-12f);
    float ks = 1.0f / fmaxf(sqrtf(ssk), 1e-12f);

    size_t ob = ((size_t)(b * H_ + h) * L_ + l) * 64 + lane * 2;
    *(float2*)(Q  + ob) = make_float2(qv.x * qs, qv.y * qs);
    *(float2*)(Ko + ob) = make_float2(kv.x * ks, kv.y * ks);
    *(float2*)(V  + ob) = vv;
}

// ---------------- attention: BIG segments (8: ln=169, 9: ln=256) ----------------
// 512 threads; lane-PAIRS split one query: thread handles 32 of 64 dims.
// QK partial merged with shfl_xor(.,1). 16 warps/SM (vs 8) on 85% of the
// attention FLOPs. Compute runs unguarded (reads in-bounds); stores guarded.
__global__ __launch_bounds__(512)
void attn_big_kernel(const float* __restrict__ Q, const float* __restrict__ Kn,
                     const float* __restrict__ V, const float* __restrict__ sl,
                     float* __restrict__ Att)
{
    extern __shared__ float smdyn[];
    const int cta = blockIdx.x;
    const int seg = 9 - (cta >> 8);          // 0..255 -> seg 9, 256..511 -> seg 8
    const int hb  = cta & 255;
    const int h = hb & 15, b = hb >> 4;

    const int ln    = (seg == 9) ? 256 : 169;
    const int start = (seg == 9) ? 424 : 255;

    float* Ks = smdyn;
    float* Vs = smdyn + ln * 64;
    const int tid = threadIdx.x;
    const size_t base = ((size_t)(b * H_ + h) * L_ + start) * 64;

    for (int idx = tid * 4; idx < ln * 64; idx += 2048) {
        *(float4*)&Ks[idx] = *(const float4*)&Kn[base + idx];
        *(float4*)&Vs[idx] = *(const float4*)&V[base + idx];
    }
    const float mfix = expf(fminf(sl[h], MAXLOG));
    __syncthreads();

    const int qi = tid >> 1;           // query row (0..255)
    const int half = tid & 1;          // which 32-dim half
    const int hofs = half * 32;        // float offset of this half

    u64 qp[16], op[16];
    {   // reads are in-bounds even for qi >= ln (stays inside this (b,h) plane)
        const u64* qg = (const u64*)(Q + base + (size_t)qi * 64 + hofs);
        #pragma unroll
        for (int t = 0; t < 16; t++) { qp[t] = qg[t]; op[t] = 0ull; }
    }

    float lsum = 0.f;
    for (int j = 0; j < ln; j++) {
        const u64* kp = (const u64*)(Ks + j * 64 + hofs);
        u64 s4[4] = {0ull, 0ull, 0ull, 0ull};
        #pragma unroll
        for (int t = 0; t < 16; t++) pfma(s4[t & 3], qp[t], kp[t]);
        float2 f0 = up2(s4[0]), f1 = up2(s4[1]), f2 = up2(s4[2]), f3 = up2(s4[3]);
        float tot = ((f0.x + f0.y) + (f1.x + f1.y)) + ((f2.x + f2.y) + (f3.x + f3.y));
        tot += __shfl_xor_sync(0xffffffffu, tot, 1);   // merge lane-pair halves
        float p = __expf(tot - mfix);
        lsum += p;
        u64 pp = pk2(p, p);
        const u64* vp = (const u64*)(Vs + j * 64 + hofs);
        #pragma unroll
        for (int t = 0; t < 16; t++) pfma(op[t], pp, vp[t]);
    }

    __syncthreads();              // done reading Ks -> reuse as output stage
    if (qi < ln) {
        float inv = 1.0f / lsum;
        unsigned* st = (unsigned*)Ks + qi * 64 + hofs;
        #pragma unroll
        for (int t = 0; t < 16; t++) {
            float2 f = up2(op[t]);
            st[2 * t]     = f2tf(f.x * inv);   // tf32-round: proj needs no cvt
            st[2 * t + 1] = f2tf(f.y * inv);
        }
    }
    __syncthreads();
    const size_t ob = (size_t)(b * L_ + start);
    for (int idx = tid * 4; idx < ln * 64; idx += 2048) {
        int row = idx >> 6, e = idx & 63;
        *(float4*)&Att[(ob + row) * C_ + h * 64 + e] = *(float4*)&Ks[idx];
    }
}

// ---------------- attention: SMALL segments (0..7, ln<=100) ----------------
// 128 threads, one thread per query row, 51.2 KB smem -> 4 CTAs/SM.
__global__ __launch_bounds__(128)
void attn_small_kernel(const float* __restrict__ Q, const float* __restrict__ Kn,
                       const float* __restrict__ V, const float* __restrict__ sl,
                       float* __restrict__ Att)
{
    extern __shared__ float smdyn[];
    const int cta = blockIdx.x;
    const int seg = 7 - (cta >> 8);          // bigger segs first
    const int hb  = cta & 255;
    const int h = hb & 15, b = hb >> 4;

    const int pn[8]  = {1, 4, 9, 16, 25, 36, 64, 100};
    const int off[8] = {0, 1, 5, 14, 30, 55, 91, 155};
    const int ln = pn[seg], start = off[seg];

    float* Ks = smdyn;
    float* Vs = smdyn + ln * 64;
    const int tid = threadIdx.x;
    const size_t base = ((size_t)(b * H_ + h) * L_ + start) * 64;

    for (int idx = tid * 4; idx < ln * 64; idx += 512) {
        *(float4*)&Ks[idx] = *(const float4*)&Kn[base + idx];
        *(float4*)&Vs[idx] = *(const float4*)&V[base + idx];
    }
    const float mfix = expf(fminf(sl[h], MAXLOG));
    __syncthreads();

    u64 op[32];
    float lsum = 0.f;
    if (tid < ln) {
        u64 qp[32];
        const u64* qg = (const u64*)(Q + base + (size_t)tid * 64);
        #pragma unroll
        for (int t = 0; t < 32; t++) { qp[t] = qg[t]; op[t] = 0ull; }

        for (int j = 0; j < ln; j++) {
            const u64* kp = (const u64*)(Ks + j * 64);
            u64 s8[8];
            #pragma unroll
            for (int t = 0; t < 8; t++) s8[t] = 0ull;
            #pragma unroll
            for (int t = 0; t < 32; t++) pfma(s8[t & 7], qp[t], kp[t]);

            float tot = 0.f;
            #pragma unroll
            for (int r = 0; r < 8; r++) { float2 f = up2(s8[r]); tot += f.x + f.y; }

            float p = __expf(tot - mfix);
            lsum += p;
            u64 pp = pk2(p, p);

            const u64* vp = (const u64*)(Vs + j * 64);
            #pragma unroll
            for (int t = 0; t < 32; t++) pfma(op[t], pp, vp[t]);
        }
    }
    __syncthreads();
    if (tid < ln) {
        float inv = 1.0f / lsum;
        #pragma unroll
        for (int t = 0; t < 32; t++) {
            float2 f = up2(op[t]);
            ((unsigned*)Ks)[tid * 64 + 2 * t]     = f2tf(f.x * inv);
            ((unsigned*)Ks)[tid * 64 + 2 * t + 1] = f2tf(f.y * inv);
        }
    }
    __syncthreads();
    const size_t ob = (size_t)(b * L_ + start);
    for (int idx = tid * 4; idx < ln * 64; idx += 512) {
        int row = idx >> 6, e = idx & 63;
        *(float4*)&Att[(ob + row) * C_ + h * 64 + e] = *(float4*)&Ks[idx];
    }
}

// ---------------- launch ----------------
extern "C" void kernel_launch(void* const* d_in, const int* in_sizes, int n_in,
                              void* d_out, int out_size)
{
    const float* x    = (const float*)d_in[0];
    // d_in[1] = patch_nums (fixed for this problem; offsets compiled in)
    const float* wqkv = (const float*)d_in[2];
    const float* qb   = (const float*)d_in[3];
    const float* vb   = (const float*)d_in[4];
    const float* slog = (const float*)d_in[5];
    const float* wp   = (const float*)d_in[6];
    const float* pb   = (const float*)d_in[7];
    float* out = (float*)d_out;

    float *qkv, *q, *k, *v, *att, *xr, *wqkvr, *wpr;
    cudaGetSymbolAddress((void**)&qkv,   g_qkv);
    cudaGetSymbolAddress((void**)&q,     g_q);
    cudaGetSymbolAddress((void**)&k,     g_k);
    cudaGetSymbolAddress((void**)&v,     g_v);
    cudaGetSymbolAddress((void**)&att,   g_att);
    cudaGetSymbolAddress((void**)&xr,    g_xr);
    cudaGetSymbolAddress((void**)&wqkvr, g_wqkvr);
    cudaGetSymbolAddress((void**)&wpr,   g_wpr);

    const int attn_small_smem = 2 * 100 * 64 * (int)sizeof(float);  // 51200 B
    const int attn_big_smem   = 2 * 256 * 64 * (int)sizeof(float);  // 131072 B
    cudaFuncSetAttribute(gemm_tf32_kernel,
                         cudaFuncAttributeMaxDynamicSharedMemorySize, GEMM_SMEM);
    cudaFuncSetAttribute(attn_big_kernel,
                         cudaFuncAttributeMaxDynamicSharedMemorySize, attn_big_smem);
    cudaFuncSetAttribute(attn_small_kernel,
                         cudaFuncAttributeMaxDynamicSharedMemorySize, attn_small_smem);

    // 0) pre-round GEMM operands to tf32 (GEMM hot loops are cvt-free)
    {
        const int nx = M_ * C_, nw1 = N1_ * C_, nw2 = C_ * C_;
        round_tf32_kernel<<<nx  / 1024, 256>>>(x,    xr,    nx);
        round_tf32_kernel<<<nw1 / 1024, 256>>>(wqkv, wqkvr, nw1);
        round_tf32_kernel<<<nw2 / 1024, 256>>>(wp,   wpr,   nw2);
    }

    // 1) QKV projection (tf32 mma.sync, 3-stage cp.async, 1 barrier/chunk)
    gemm_tf32_kernel<<<dim3(N1_ / 128, M_ / 128), 256, GEMM_SMEM>>>(
        xr, wqkvr, qb, vb, qkv, N1_, C_, 1);

    // 2) l2norm q/k + per-head scale + transpose to [B,H,L,D]
    norm_kernel<<<(M_ * H_) / 8, 256>>>(qkv, slog, q, k, v);

    // 3) block-diagonal attention: big segs (pair-split, 16 warps/SM),
    //    then small segs (4 CTAs/SM)
    attn_big_kernel<<<512, 512, attn_big_smem>>>(q, k, v, slog, att);
    attn_small_kernel<<<2048, 128, attn_small_smem>>>(q, k, v, slog, att);

    // 4) output projection (tf32 mma.sync) -> d_out
    gemm_tf32_kernel<<<dim3(C_ / 128, M_ / 128), 256, GEMM_SMEM>>>(
        att, wpr, pb, nullptr, out, C_, C_, 0);
}

// round 14
// speedup vs baseline: 1.2407x; 1.2407x over previous
#include <cuda_runtime.h>
#include <cstdint>

// Problem constants
#define B_ 16
#define L_ 680
#define C_ 1024
#define H_ 16
#define D_ 64
#define M_ (B_ * L_)     // 10880
#define N1_ (3 * C_)     // 3072
#define MAXLOG 4.605170185988091f   // ln(100)

// ---------------- scratch (static __device__, no allocations) ----------------
__device__ float g_qkv[(size_t)M_ * N1_];          // GEMM1 output [M, 3C]
__device__ float g_q[(size_t)B_ * H_ * L_ * D_];   // normalized q, [B,H,L,D]
__device__ float g_k[(size_t)B_ * H_ * L_ * D_];
__device__ float g_v[(size_t)B_ * H_ * L_ * D_];
__device__ float g_att[(size_t)M_ * C_];           // attention out (tf32-rounded)
__device__ float g_xr[(size_t)M_ * C_];            // x rounded to tf32
__device__ float g_wqkvr[(size_t)N1_ * C_];        // wqkv rounded to tf32
__device__ float g_wpr[(size_t)C_ * C_];           // wp rounded to tf32

// ---------------- helpers ----------------
__device__ __forceinline__ unsigned f2tf(float x) {
    unsigned r;
    asm("cvt.rna.tf32.f32 %0, %1;" : "=r"(r) : "f"(x));
    return r;
}

__device__ __forceinline__ void mma_tf32(float c[4], const unsigned a[4],
                                         unsigned b0, unsigned b1) {
    asm volatile(
        "mma.sync.aligned.m16n8k8.row.col.f32.tf32.tf32.f32 "
        "{%0,%1,%2,%3}, {%4,%5,%6,%7}, {%8,%9}, {%0,%1,%2,%3};"
        : "+f"(c[0]), "+f"(c[1]), "+f"(c[2]), "+f"(c[3])
        : "r"(a[0]), "r"(a[1]), "r"(a[2]), "r"(a[3]), "r"(b0), "r"(b1));
}

// ldmatrix: each m8n8.b16 matrix = one 8x4 tile of b32; thread t gets [t>>2][t&3]
__device__ __forceinline__ void ldsm4(unsigned r[4], uint32_t addr) {
    asm volatile("ldmatrix.sync.aligned.m8n8.x4.shared.b16 {%0,%1,%2,%3}, [%4];"
                 : "=r"(r[0]), "=r"(r[1]), "=r"(r[2]), "=r"(r[3]) : "r"(addr));
}
__device__ __forceinline__ void ldsm2(unsigned& r0, unsigned& r1, uint32_t addr) {
    asm volatile("ldmatrix.sync.aligned.m8n8.x2.shared.b16 {%0,%1}, [%2];"
                 : "=r"(r0), "=r"(r1) : "r"(addr));
}

__device__ __forceinline__ void cp16(unsigned* s, const float* g) {
    unsigned sa = (unsigned)__cvta_generic_to_shared(s);
    asm volatile("cp.async.cg.shared.global [%0], [%1], 16;" :: "r"(sa), "l"(g));
}
__device__ __forceinline__ void cp_commit() {
    asm volatile("cp.async.commit_group;");
}
template<int N> __device__ __forceinline__ void cp_wait() {
    asm volatile("cp.async.wait_group %0;" :: "n"(N));
}

// packed f32x2 primitives — operands STAY packed (no movs in hot loops)
typedef unsigned long long u64;
__device__ __forceinline__ void pfma(u64& d, u64 a, u64 b) {
    asm("fma.rn.f32x2 %0, %1, %2, %0;" : "+l"(d) : "l"(a), "l"(b));
}
__device__ __forceinline__ float2 up2(u64 v) {
    float2 r; asm("mov.b64 {%0, %1}, %2;" : "=f"(r.x), "=f"(r.y) : "l"(v)); return r;
}
__device__ __forceinline__ u64 pk2(float x, float y) {
    u64 r; asm("mov.b64 %0, {%1, %2};" : "=l"(r) : "f"(x), "f"(y)); return r;
}

// ---------------- tf32 pre-round (elementwise) ----------------
__global__ __launch_bounds__(256)
void round_tf32_kernel(const float* __restrict__ src, float* __restrict__ dst, int n)
{
    int i = (blockIdx.x * 256 + threadIdx.x) * 4;
    if (i < n) {
        float4 v = *(const float4*)(src + i);
        uint4 r = make_uint4(f2tf(v.x), f2tf(v.y), f2tf(v.z), f2tf(v.w));
        *(uint4*)(dst + i) = r;
    }
}

// ---------------- GEMM: C[m,n] = sum_k A[m,k]*W[n,k] + bias(n) ----------------
// Pre-rounded tf32 inputs; no cvt in hot loop. 256 threads (8 warps),
// CTA tile 128x128, warp tile 64x32. 3-stage cp.async, ONE barrier per chunk.
// Fragments via ldmatrix (8 LDSM vs 24 LDS.32 per warp-step).
// mode 0: bias = b0p[n]   (proj)
// mode 1: qkv bias: n<1024 -> b0p[n]; n<2048 -> 0; else b1p[n-2048]
#define SROW 36                       // +4 pad: LDSM rows land on banks 0,4,..,28
#define STAGEF (2 * 128 * SROW)       // words per stage (A then B)
#define GEMM_SMEM (3 * STAGEF * 4)    // 110592 B

__global__ __launch_bounds__(256, 2)
void gemm_tf32_kernel(const float* __restrict__ A, const float* __restrict__ W,
                      const float* __restrict__ b0p, const float* __restrict__ b1p,
                      float* __restrict__ Cout, int N, int K, int mode)
{
    extern __shared__ unsigned sm[];
    const uint32_t smb = (uint32_t)__cvta_generic_to_shared(sm);

    const int bm = blockIdx.y * 128, bn = blockIdx.x * 128;
    const int tid  = threadIdx.x;
    const int lane = tid & 31, warp = tid >> 5;
    const int wm = (warp & 1) * 64;    // 2 warps along m
    const int wn = (warp >> 1) * 32;   // 4 warps along n
    const int gid = lane >> 2, tig = lane & 3;
    const int lrow = tid >> 3;         // 0..31
    const int lcol = (tid & 7) * 4;    // 0,4,...,28

    // ldmatrix per-thread row addresses (word offsets within a stage)
    const int a_off = (wm + (lane & 15)) * SROW + (lane >> 4) * 4;
    const int b_off = (wn + (lane & 7))  * SROW + ((lane >> 3) & 1) * 4;

    float acc[4][4][4];
    #pragma unroll
    for (int mt = 0; mt < 4; mt++)
        #pragma unroll
        for (int nt = 0; nt < 4; nt++)
            #pragma unroll
            for (int r = 0; r < 4; r++) acc[mt][nt][r] = 0.f;

    const float* Ag = A + (size_t)(bm + lrow) * K + lcol;
    const float* Wg = W + (size_t)(bn + lrow) * K + lcol;

    const int NCH = K >> 5;            // 32-wide k chunks

    auto load_chunk = [&](int c, int s) {
        unsigned* sA = sm + s * STAGEF;
        unsigned* sB = sA + 128 * SROW;
        const float* Ap = Ag + (size_t)c * 32;
        const float* Wp = Wg + (size_t)c * 32;
        #pragma unroll
        for (int i = 0; i < 4; i++) {
            cp16(&sA[(lrow + i * 32) * SROW + lcol], Ap + (size_t)i * 32 * K);
            cp16(&sB[(lrow + i * 32) * SROW + lcol], Wp + (size_t)i * 32 * K);
        }
        cp_commit();
    };

    // prologue: stage 0 <- chunk 0, stage 1 <- chunk 1
    load_chunk(0, 0);
    load_chunk(1, 1);

    int scur = 0;                      // stage of chunk `it`
    for (int it = 0; it < NCH; it++) {
        if (it < NCH - 1) cp_wait<1>(); else cp_wait<0>();
        __syncthreads();               // chunk `it` visible; chunk `it-1` fully read

        if (it + 2 < NCH) {
            int snx = scur + 2; if (snx >= 3) snx -= 3;
            load_chunk(it + 2, snx);   // refills the stage consumed at it-1
        }

        const uint32_t aS = smb + (uint32_t)(scur * STAGEF) * 4u;
        const uint32_t bS = aS + 128u * SROW * 4u;
        const uint32_t aAdr = aS + (uint32_t)a_off * 4u;
        const uint32_t bAdr = bS + (uint32_t)b_off * 4u;

        #pragma unroll
        for (int ks = 0; ks < 32; ks += 8) {
            unsigned a[4][4];
            #pragma unroll
            for (int mt = 0; mt < 4; mt++)
                ldsm4(a[mt], aAdr + (uint32_t)(mt * 16 * SROW + ks) * 4u);
            #pragma unroll
            for (int nt = 0; nt < 4; nt++) {
                unsigned b0, b1;
                ldsm2(b0, b1, bAdr + (uint32_t)(nt * 8 * SROW + ks) * 4u);
                #pragma unroll
                for (int mt = 0; mt < 4; mt++)
                    mma_tf32(acc[mt][nt], a[mt], b0, b1);
            }
        }
        scur = scur + 1; if (scur >= 3) scur = 0;
    }

    #pragma unroll
    for (int mt = 0; mt < 4; mt++) {
        #pragma unroll
        for (int nt = 0; nt < 4; nt++) {
            int row = bm + wm + mt * 16 + gid;
            int col = bn + wn + nt * 8 + 2 * tig;
            float bz0, bz1;
            if (mode == 0) {
                bz0 = b0p[col]; bz1 = b0p[col + 1];
            } else {
                if (col < 1024)       { bz0 = b0p[col];        bz1 = b0p[col + 1]; }
                else if (col < 2048)  { bz0 = 0.f;             bz1 = 0.f; }
                else                  { bz0 = b1p[col - 2048]; bz1 = b1p[col - 2047]; }
            }
            *(float2*)&Cout[(size_t)row * N + col] =
                make_float2(acc[mt][nt][0] + bz0, acc[mt][nt][1] + bz1);
            *(float2*)&Cout[(size_t)(row + 8) * N + col] =
                make_float2(acc[mt][nt][2] + bz0, acc[mt][nt][3] + bz1);
        }
    }
}

// ---------------- l2norm + scale + transpose to [B,H,L,D] ----------------
__global__ __launch_bounds__(256)
void norm_kernel(const float* __restrict__ Y, const float* __restrict__ sl,
                 float* __restrict__ Q, float* __restrict__ Ko, float* __restrict__ V)
{
    int w    = blockIdx.x * 8 + (threadIdx.x >> 5);   // one warp per (m,h)
    int lane = threadIdx.x & 31;
    int m = w >> 4, h = w & 15;
    int b = m / L_, l = m % L_;

    const float* row = Y + (size_t)m * N1_ + h * 64 + lane * 2;
    float2 qv = *(const float2*)(row);
    float2 kv = *(const float2*)(row + 1024);
    float2 vv = *(const float2*)(row + 2048);

    float ssq = qv.x * qv.x + qv.y * qv.y;
    float ssk = kv.x * kv.x + kv.y * kv.y;
    #pragma unroll
    for (int o = 16; o; o >>= 1) {
        ssq += __shfl_xor_sync(0xffffffffu, ssq, o);
        ssk += __shfl_xor_sync(0xffffffffu, ssk, o);
    }
    float qs = expf(fminf(sl[h], MAXLOG)) / fmaxf(sqrtf(ssq), 1e-12f);
    float ks = 1.0f / fmaxf(sqrtf(ssk), 1e-12f);

    size_t ob = ((size_t)(b * H_ + h) * L_ + l) * 64 + lane * 2;
    *(float2*)(Q  + ob) = make_float2(qv.x * qs, qv.y * qs);
    *(float2*)(Ko + ob) = make_float2(kv.x * ks, kv.y * ks);
    *(float2*)(V  + ob) = vv;
}

// ---------------- block-diagonal attention (R12 form — known good) ----------
// seg_hi - (blockIdx.x >> 8) selects segment (256 (b,h) pairs per segment).
// Two launches: big segs 8..9 (256 thr, 128 KB), small segs 0..7 (128 thr,
// 51.2 KB -> 4 CTAs/SM). thread i = query row i. |q| = scale, |k| = 1 =>
// s <= scale: fixed softmax max. Output tf32-rounded at store.
__global__ void attn_kernel(const float* __restrict__ Q, const float* __restrict__ Kn,
                            const float* __restrict__ V, const float* __restrict__ sl,
                            float* __restrict__ Att, int seg_hi)
{
    extern __shared__ float smdyn[];
    const int cta = blockIdx.x;
    const int seg = seg_hi - (cta >> 8);     // bigger segs first
    const int hb  = cta & 255;
    const int h = hb & 15, b = hb >> 4;

    const int pn[10]  = {1, 4, 9, 16, 25, 36, 64, 100, 169, 256};
    const int off[10] = {0, 1, 5, 14, 30, 55, 91, 155, 255, 424};
    const int ln = pn[seg], start = off[seg];

    float* Ks = smdyn;
    float* Vs = smdyn + ln * 64;
    const int tid = threadIdx.x;
    const int nthr4 = blockDim.x * 4;
    const size_t base = ((size_t)(b * H_ + h) * L_ + start) * 64;

    for (int idx = tid * 4; idx < ln * 64; idx += nthr4) {
        *(float4*)&Ks[idx] = *(const float4*)&Kn[base + idx];
        *(float4*)&Vs[idx] = *(const float4*)&V[base + idx];
    }
    const float mfix = expf(fminf(sl[h], MAXLOG));
    __syncthreads();

    u64 op[32];
    float lsum = 0.f;
    if (tid < ln) {
        u64 qp[32];
        const u64* qg = (const u64*)(Q + base + (size_t)tid * 64);
        #pragma unroll
        for (int t = 0; t < 32; t++) { qp[t] = qg[t]; op[t] = 0ull; }

        for (int j = 0; j < ln; j++) {
            const u64* kp = (const u64*)(Ks + j * 64);
            u64 s8[8];
            #pragma unroll
            for (int t = 0; t < 8; t++) s8[t] = 0ull;
            #pragma unroll
            for (int t = 0; t < 32; t++) pfma(s8[t & 7], qp[t], kp[t]);

            float tot = 0.f;
            #pragma unroll
            for (int r = 0; r < 8; r++) { float2 f = up2(s8[r]); tot += f.x + f.y; }

            float p = __expf(tot - mfix);
            lsum += p;
            u64 pp = pk2(p, p);

            const u64* vp = (const u64*)(Vs + j * 64);
            #pragma unroll
            for (int t = 0; t < 32; t++) pfma(op[t], pp, vp[t]);
        }
    }
    __syncthreads();              // done reading Ks -> reuse as output stage
    if (tid < ln) {
        float inv = 1.0f / lsum;
        #pragma unroll
        for (int t = 0; t < 32; t++) {
            float2 f = up2(op[t]);
            // round to tf32 here: proj GEMM consumes raw bits with no cvt
            ((unsigned*)Ks)[tid * 64 + 2 * t]     = f2tf(f.x * inv);
            ((unsigned*)Ks)[tid * 64 + 2 * t + 1] = f2tf(f.y * inv);
        }
    }
    __syncthreads();
    const size_t ob = (size_t)(b * L_ + start);
    for (int idx = tid * 4; idx < ln * 64; idx += nthr4) {
        int row = idx >> 6, e = idx & 63;
        *(float4*)&Att[(ob + row) * C_ + h * 64 + e] = *(float4*)&Ks[idx];
    }
}

// ---------------- launch ----------------
extern "C" void kernel_launch(void* const* d_in, const int* in_sizes, int n_in,
                              void* d_out, int out_size)
{
    const float* x    = (const float*)d_in[0];
    // d_in[1] = patch_nums (fixed for this problem; offsets compiled in)
    const float* wqkv = (const float*)d_in[2];
    const float* qb   = (const float*)d_in[3];
    const float* vb   = (const float*)d_in[4];
    const float* slog = (const float*)d_in[5];
    const float* wp   = (const float*)d_in[6];
    const float* pb   = (const float*)d_in[7];
    float* out = (float*)d_out;

    float *qkv, *q, *k, *v, *att, *xr, *wqkvr, *wpr;
    cudaGetSymbolAddress((void**)&qkv,   g_qkv);
    cudaGetSymbolAddress((void**)&q,     g_q);
    cudaGetSymbolAddress((void**)&k,     g_k);
    cudaGetSymbolAddress((void**)&v,     g_v);
    cudaGetSymbolAddress((void**)&att,   g_att);
    cudaGetSymbolAddress((void**)&xr,    g_xr);
    cudaGetSymbolAddress((void**)&wqkvr, g_wqkvr);
    cudaGetSymbolAddress((void**)&wpr,   g_wpr);

    const int attn_small_smem = 2 * 100 * 64 * (int)sizeof(float);  // 51200 B
    const int attn_big_smem   = 2 * 256 * 64 * (int)sizeof(float);  // 131072 B
    cudaFuncSetAttribute(gemm_tf32_kernel,
                         cudaFuncAttributeMaxDynamicSharedMemorySize, GEMM_SMEM);
    cudaFuncSetAttribute(attn_kernel,
                         cudaFuncAttributeMaxDynamicSharedMemorySize, attn_big_smem);

    // 0) pre-round GEMM operands to tf32 (GEMM hot loops are cvt-free)
    {
        const int nx = M_ * C_, nw1 = N1_ * C_, nw2 = C_ * C_;
        round_tf32_kernel<<<nx  / 1024, 256>>>(x,    xr,    nx);
        round_tf32_kernel<<<nw1 / 1024, 256>>>(wqkv, wqkvr, nw1);
        round_tf32_kernel<<<nw2 / 1024, 256>>>(wp,   wpr,   nw2);
    }

    // 1) QKV projection (tf32 mma.sync, 3-stage cp.async, ldmatrix fragments)
    gemm_tf32_kernel<<<dim3(N1_ / 128, M_ / 128), 256, GEMM_SMEM>>>(
        xr, wqkvr, qb, vb, qkv, N1_, C_, 1);

    // 2) l2norm q/k + per-head scale + transpose to [B,H,L,D]
    norm_kernel<<<(M_ * H_) / 8, 256>>>(qkv, slog, q, k, v);

    // 3) block-diagonal attention: big segs (128 KB), then small segs
    //    (51.2 KB -> 4 CTAs/SM) — the R12 configuration (fastest so far)
    attn_kernel<<<512, 256, attn_big_smem>>>(q, k, v, slog, att, 9);
    attn_kernel<<<2048, 128, attn_small_smem>>>(q, k, v, slog, att, 7);

    // 4) output projection (tf32 mma.sync, ldmatrix) -> d_out
    gemm_tf32_kernel<<<dim3(C_ / 128, M_ / 128), 256, GEMM_SMEM>>>(
        att, wpr, pb, nullptr, out, C_, C_, 0);
}

// round 15
// speedup vs baseline: 1.5026x; 1.2111x over previous
#include <cuda_runtime.h>
#include <cstdint>

// Problem constants
#define B_ 16
#define L_ 680
#define C_ 1024
#define H_ 16
#define D_ 64
#define M_ (B_ * L_)     // 10880
#define N1_ (3 * C_)     // 3072
#define MAXLOG 4.605170185988091f   // ln(100)

// ---------------- scratch (static __device__, no allocations) ----------------
__device__ float g_qkv[(size_t)M_ * N1_];          // GEMM1 output [M, 3C]
__device__ float g_q[(size_t)B_ * H_ * L_ * D_];   // normalized q (tf32 bits)
__device__ float g_k[(size_t)B_ * H_ * L_ * D_];   // normalized k (tf32 bits)
__device__ float g_v[(size_t)B_ * H_ * L_ * D_];   // v (tf32 bits)
__device__ float g_att[(size_t)M_ * C_];           // attention out (tf32-rounded)
__device__ float g_xr[(size_t)M_ * C_];            // x rounded to tf32
__device__ float g_wqkvr[(size_t)N1_ * C_];        // wqkv rounded to tf32
__device__ float g_wpr[(size_t)C_ * C_];           // wp rounded to tf32

// ---------------- helpers ----------------
__device__ __forceinline__ unsigned f2tf(float x) {
    unsigned r;
    asm("cvt.rna.tf32.f32 %0, %1;" : "=r"(r) : "f"(x));
    return r;
}
__device__ __forceinline__ float tfr(float x) {     // round to tf32, as float
    return __uint_as_float(f2tf(x));
}

__device__ __forceinline__ void mma_tf32(float c[4], const unsigned a[4],
                                         unsigned b0, unsigned b1) {
    asm volatile(
        "mma.sync.aligned.m16n8k8.row.col.f32.tf32.tf32.f32 "
        "{%0,%1,%2,%3}, {%4,%5,%6,%7}, {%8,%9}, {%0,%1,%2,%3};"
        : "+f"(c[0]), "+f"(c[1]), "+f"(c[2]), "+f"(c[3])
        : "r"(a[0]), "r"(a[1]), "r"(a[2]), "r"(a[3]), "r"(b0), "r"(b1));
}

// ldmatrix: each m8n8.b16 matrix = one 8x4 tile of b32; thread t gets [t>>2][t&3]
__device__ __forceinline__ void ldsm4(unsigned r[4], uint32_t addr) {
    asm volatile("ldmatrix.sync.aligned.m8n8.x4.shared.b16 {%0,%1,%2,%3}, [%4];"
                 : "=r"(r[0]), "=r"(r[1]), "=r"(r[2]), "=r"(r[3]) : "r"(addr));
}
__device__ __forceinline__ void ldsm2(unsigned& r0, unsigned& r1, uint32_t addr) {
    asm volatile("ldmatrix.sync.aligned.m8n8.x2.shared.b16 {%0,%1}, [%2];"
                 : "=r"(r0), "=r"(r1) : "r"(addr));
}

__device__ __forceinline__ void cp16(unsigned* s, const float* g) {
    unsigned sa = (unsigned)__cvta_generic_to_shared(s);
    asm volatile("cp.async.cg.shared.global [%0], [%1], 16;" :: "r"(sa), "l"(g));
}
__device__ __forceinline__ void cp16s(uint32_t s, const float* g) {
    asm volatile("cp.async.cg.shared.global [%0], [%1], 16;" :: "r"(s), "l"(g));
}
__device__ __forceinline__ void cp_commit() {
    asm volatile("cp.async.commit_group;");
}
template<int N> __device__ __forceinline__ void cp_wait() {
    asm volatile("cp.async.wait_group %0;" :: "n"(N));
}

// packed f32x2 primitives — operands STAY packed (no movs in hot loops)
typedef unsigned long long u64;
__device__ __forceinline__ void pfma(u64& d, u64 a, u64 b) {
    asm("fma.rn.f32x2 %0, %1, %2, %0;" : "+l"(d) : "l"(a), "l"(b));
}
__device__ __forceinline__ float2 up2(u64 v) {
    float2 r; asm("mov.b64 {%0, %1}, %2;" : "=f"(r.x), "=f"(r.y) : "l"(v)); return r;
}
__device__ __forceinline__ u64 pk2(float x, float y) {
    u64 r; asm("mov.b64 %0, {%1, %2};" : "=l"(r) : "f"(x), "f"(y)); return r;
}

// ---------------- tf32 pre-round (elementwise) ----------------
__global__ __launch_bounds__(256)
void round_tf32_kernel(const float* __restrict__ src, float* __restrict__ dst, int n)
{
    int i = (blockIdx.x * 256 + threadIdx.x) * 4;
    if (i < n) {
        float4 v = *(const float4*)(src + i);
        uint4 r = make_uint4(f2tf(v.x), f2tf(v.y), f2tf(v.z), f2tf(v.w));
        *(uint4*)(dst + i) = r;
    }
}

// ---------------- GEMM: C[m,n] = sum_k A[m,k]*W[n,k] + bias(n) ----------------
// (R14 form: pre-rounded tf32 inputs, 3-stage cp.async, ldmatrix fragments)
#define SROW 36
#define STAGEF (2 * 128 * SROW)
#define GEMM_SMEM (3 * STAGEF * 4)    // 110592 B

__global__ __launch_bounds__(256, 2)
void gemm_tf32_kernel(const float* __restrict__ A, const float* __restrict__ W,
                      const float* __restrict__ b0p, const float* __restrict__ b1p,
                      float* __restrict__ Cout, int N, int K, int mode)
{
    extern __shared__ unsigned sm[];
    const uint32_t smb = (uint32_t)__cvta_generic_to_shared(sm);

    const int bm = blockIdx.y * 128, bn = blockIdx.x * 128;
    const int tid  = threadIdx.x;
    const int lane = tid & 31, warp = tid >> 5;
    const int wm = (warp & 1) * 64;
    const int wn = (warp >> 1) * 32;
    const int gid = lane >> 2, tig = lane & 3;
    const int lrow = tid >> 3;
    const int lcol = (tid & 7) * 4;

    const int a_off = (wm + (lane & 15)) * SROW + (lane >> 4) * 4;
    const int b_off = (wn + (lane & 7))  * SROW + ((lane >> 3) & 1) * 4;

    float acc[4][4][4];
    #pragma unroll
    for (int mt = 0; mt < 4; mt++)
        #pragma unroll
        for (int nt = 0; nt < 4; nt++)
            #pragma unroll
            for (int r = 0; r < 4; r++) acc[mt][nt][r] = 0.f;

    const float* Ag = A + (size_t)(bm + lrow) * K + lcol;
    const float* Wg = W + (size_t)(bn + lrow) * K + lcol;

    const int NCH = K >> 5;

    auto load_chunk = [&](int c, int s) {
        unsigned* sA = sm + s * STAGEF;
        unsigned* sB = sA + 128 * SROW;
        const float* Ap = Ag + (size_t)c * 32;
        const float* Wp = Wg + (size_t)c * 32;
        #pragma unroll
        for (int i = 0; i < 4; i++) {
            cp16(&sA[(lrow + i * 32) * SROW + lcol], Ap + (size_t)i * 32 * K);
            cp16(&sB[(lrow + i * 32) * SROW + lcol], Wp + (size_t)i * 32 * K);
        }
        cp_commit();
    };

    load_chunk(0, 0);
    load_chunk(1, 1);

    int scur = 0;
    for (int it = 0; it < NCH; it++) {
        if (it < NCH - 1) cp_wait<1>(); else cp_wait<0>();
        __syncthreads();

        if (it + 2 < NCH) {
            int snx = scur + 2; if (snx >= 3) snx -= 3;
            load_chunk(it + 2, snx);
        }

        const uint32_t aS = smb + (uint32_t)(scur * STAGEF) * 4u;
        const uint32_t bS = aS + 128u * SROW * 4u;
        const uint32_t aAdr = aS + (uint32_t)a_off * 4u;
        const uint32_t bAdr = bS + (uint32_t)b_off * 4u;

        #pragma unroll
        for (int ks = 0; ks < 32; ks += 8) {
            unsigned a[4][4];
            #pragma unroll
            for (int mt = 0; mt < 4; mt++)
                ldsm4(a[mt], aAdr + (uint32_t)(mt * 16 * SROW + ks) * 4u);
            #pragma unroll
            for (int nt = 0; nt < 4; nt++) {
                unsigned b0, b1;
                ldsm2(b0, b1, bAdr + (uint32_t)(nt * 8 * SROW + ks) * 4u);
                #pragma unroll
                for (int mt = 0; mt < 4; mt++)
                    mma_tf32(acc[mt][nt], a[mt], b0, b1);
            }
        }
        scur = scur + 1; if (scur >= 3) scur = 0;
    }

    #pragma unroll
    for (int mt = 0; mt < 4; mt++) {
        #pragma unroll
        for (int nt = 0; nt < 4; nt++) {
            int row = bm + wm + mt * 16 + gid;
            int col = bn + wn + nt * 8 + 2 * tig;
            float bz0, bz1;
            if (mode == 0) {
                bz0 = b0p[col]; bz1 = b0p[col + 1];
            } else {
                if (col < 1024)       { bz0 = b0p[col];        bz1 = b0p[col + 1]; }
                else if (col < 2048)  { bz0 = 0.f;             bz1 = 0.f; }
                else                  { bz0 = b1p[col - 2048]; bz1 = b1p[col - 2047]; }
            }
            *(float2*)&Cout[(size_t)row * N + col] =
                make_float2(acc[mt][nt][0] + bz0, acc[mt][nt][1] + bz1);
            *(float2*)&Cout[(size_t)(row + 8) * N + col] =
                make_float2(acc[mt][nt][2] + bz0, acc[mt][nt][3] + bz1);
        }
    }
}

// ---------------- l2norm + scale + transpose to [B,H,L,D] ----------------
// Outputs are tf32-rounded (RNA) so the MMA attention consumes valid tf32.
__global__ __launch_bounds__(256)
void norm_kernel(const float* __restrict__ Y, const float* __restrict__ sl,
                 float* __restrict__ Q, float* __restrict__ Ko, float* __restrict__ V)
{
    int w    = blockIdx.x * 8 + (threadIdx.x >> 5);   // one warp per (m,h)
    int lane = threadIdx.x & 31;
    int m = w >> 4, h = w & 15;
    int b = m / L_, l = m % L_;

    const float* row = Y + (size_t)m * N1_ + h * 64 + lane * 2;
    float2 qv = *(const float2*)(row);
    float2 kv = *(const float2*)(row + 1024);
    float2 vv = *(const float2*)(row + 2048);

    float ssq = qv.x * qv.x + qv.y * qv.y;
    float ssk = kv.x * kv.x + kv.y * kv.y;
    #pragma unroll
    for (int o = 16; o; o >>= 1) {
        ssq += __shfl_xor_sync(0xffffffffu, ssq, o);
        ssk += __shfl_xor_sync(0xffffffffu, ssk, o);
    }
    float qs = expf(fminf(sl[h], MAXLOG)) / fmaxf(sqrtf(ssq), 1e-12f);
    float ks = 1.0f / fmaxf(sqrtf(ssk), 1e-12f);

    size_t ob = ((size_t)(b * H_ + h) * L_ + l) * 64 + lane * 2;
    *(uint2*)(Q  + ob) = make_uint2(f2tf(qv.x * qs), f2tf(qv.y * qs));
    *(uint2*)(Ko + ob) = make_uint2(f2tf(kv.x * ks), f2tf(kv.y * ks));
    *(uint2*)(V  + ob) = make_uint2(f2tf(vv.x),      f2tf(vv.y));
}

// ---------------- attention, BIG segments (8: ln=169, 9: ln=256) — MMA ------
// One CTA per (b,h,seg); 8 warps; warp = 32 query rows. K/V tiles of 32 keys
// double-buffered via cp.async (rows padded to 68 words). S = Q K^T via
// m16n8k8 tf32 (Q frags in regs, K via ldmatrix). Fixed-max softmax (|s| <=
// scale) -> exp is elementwise, no rescale. P staged per-warp in smem
// (tf32-rounded; used for BOTH numerator and lsum so truncation bias cancels),
// reloaded via ldmatrix as A frags. O += P V with V B-frags as scalar LDS.
// Tail masking (p = 0 for j >= ln) makes seg 8 exact.
// smem (words): K stage s @ s*2176 | V stage s @ 4352+s*2176 | P @ 8704+warp*1152
#define ATT_SMEM 71680

__global__ __launch_bounds__(256)
void attn_mma_kernel(const float* __restrict__ Q, const float* __restrict__ Kn,
                     const float* __restrict__ V, const float* __restrict__ sl,
                     float* __restrict__ Att)
{
    extern __shared__ unsigned sm[];
    const uint32_t smb = (uint32_t)__cvta_generic_to_shared(sm);

    const int cta = blockIdx.x;
    const int is9 = (cta >> 8) == 0;
    const int ln    = is9 ? 256 : 169;
    const int start = is9 ? 424 : 255;
    const int hb = cta & 255;
    const int h = hb & 15, b = hb >> 4;

    const int tid = threadIdx.x;
    const int warp = tid >> 5, lane = tid & 31;
    const int gid = lane >> 2, tig = lane & 3;

    const size_t base = ((size_t)(b * H_ + h) * L_ + start) * 64;
    const float* Kg = Kn + base;
    const float* Vg = V + base;

    // Q fragments for rows warp*32 .. warp*32+31 (in-bounds: start+256 <= 680)
    unsigned qa[2][8][4];
    {
        const unsigned* Qg = (const unsigned*)(Q + base);
        #pragma unroll
        for (int mt = 0; mt < 2; mt++)
            #pragma unroll
            for (int kt = 0; kt < 8; kt++)
                #pragma unroll
                for (int i = 0; i < 4; i++) {
                    int row = warp * 32 + mt * 16 + gid + (i & 1) * 8;
                    int col = kt * 8 + tig + (i >> 1) * 4;
                    qa[mt][kt][i] = Qg[row * 64 + col];
                }
    }

    float oAcc[2][8][4];
    #pragma unroll
    for (int mt = 0; mt < 2; mt++)
        #pragma unroll
        for (int nt = 0; nt < 8; nt++)
            #pragma unroll
            for (int r = 0; r < 4; r++) oAcc[mt][nt][r] = 0.f;

    float lsum[2][2] = {{0.f, 0.f}, {0.f, 0.f}};
    const float mfix = expf(fminf(sl[h], MAXLOG));

    const int njt = (ln + 31) >> 5;

    auto load_kv = [&](int jt, int s) {
        int j0 = jt * 32;
        int r = tid >> 4, g = (tid & 15) * 4;
        const float* Kp = Kg + (size_t)(j0 + r) * 64 + g;
        const float* Vp = Vg + (size_t)(j0 + r) * 64 + g;
        uint32_t kd = smb + (uint32_t)(s * 2176 + r * 68 + g) * 4u;
        uint32_t vd = kd + 4352u * 4u;
        cp16s(kd,                 Kp);
        cp16s(kd + 16u * 68u * 4u, Kp + 16 * 64);
        cp16s(vd,                 Vp);
        cp16s(vd + 16u * 68u * 4u, Vp + 16 * 64);
        cp_commit();
    };

    load_kv(0, 0);
    load_kv(1, 1);

    const int krow = (lane & 7) + ((lane >> 4) << 3);
    const int kc4  = ((lane >> 3) & 1) << 2;
    const int prow = lane & 15;
    const int pc4  = (lane >> 4) << 2;
    const uint32_t pb = smb + (8704u + (uint32_t)warp * 1152u) * 4u;

    for (int jt = 0; jt < njt; jt++) {
        if (jt + 1 < njt) cp_wait<1>(); else cp_wait<0>();
        __syncthreads();
        const uint32_t ks = smb + (uint32_t)((jt & 1) * 2176) * 4u;
        const unsigned* vs = sm + 4352 + (jt & 1) * 2176;

        // ---- S = Q K^T (32 q rows x 32 keys per warp) ----
        float sA[2][4][4];
        #pragma unroll
        for (int mt = 0; mt < 2; mt++)
            #pragma unroll
            for (int nt = 0; nt < 4; nt++)
                #pragma unroll
                for (int r = 0; r < 4; r++) sA[mt][nt][r] = 0.f;

        #pragma unroll
        for (int kt = 0; kt < 8; kt++) {
            #pragma unroll
            for (int p = 0; p < 2; p++) {
                unsigned bb[4];
                ldsm4(bb, ks + (uint32_t)((p * 16 + krow) * 68 + kt * 8 + kc4) * 4u);
                #pragma unroll
                for (int mt = 0; mt < 2; mt++) {
                    mma_tf32(sA[mt][2 * p],     qa[mt][kt], bb[0], bb[1]);
                    mma_tf32(sA[mt][2 * p + 1], qa[mt][kt], bb[2], bb[3]);
                }
            }
        }

        // ---- exp (fixed max), mask tail, lsum, stage P (tf32-rounded) ----
        float2* P2 = (float2*)(sm + 8704 + warp * 1152);
        #pragma unroll
        for (int mt = 0; mt < 2; mt++)
            #pragma unroll
            for (int nt = 0; nt < 4; nt++) {
                int jj = jt * 32 + nt * 8 + 2 * tig;
                float p0 = (jj     < ln) ? tfr(__expf(sA[mt][nt][0] - mfix)) : 0.f;
                float p1 = (jj + 1 < ln) ? tfr(__expf(sA[mt][nt][1] - mfix)) : 0.f;
                float p2 = (jj     < ln) ? tfr(__expf(sA[mt][nt][2] - mfix)) : 0.f;
                float p3 = (jj + 1 < ln) ? tfr(__expf(sA[mt][nt][3] - mfix)) : 0.f;
                lsum[mt][0] += p0 + p1;
                lsum[mt][1] += p2 + p3;
                int w0 = ((mt * 16 + gid) * 36 + nt * 8 + 2 * tig) >> 1;
                P2[w0]             = make_float2(p0, p1);
                P2[w0 + 4 * 36]    = make_float2(p2, p3);   // +8 rows
            }
        __syncwarp();

        // ---- reload P as A fragments ----
        unsigned pa[2][4][4];
        #pragma unroll
        for (int mt = 0; mt < 2; mt++)
            #pragma unroll
            for (int k2 = 0; k2 < 4; k2++)
                ldsm4(pa[mt][k2], pb + (uint32_t)((mt * 16 + prow) * 36 + k2 * 8 + pc4) * 4u);

        // ---- O += P V  (V B-frags: conflict-free scalar LDS) ----
        #pragma unroll
        for (int k2 = 0; k2 < 4; k2++) {
            #pragma unroll
            for (int nt = 0; nt < 8; nt++) {
                unsigned b0 = vs[(k2 * 8 + tig)     * 68 + nt * 8 + gid];
                unsigned b1 = vs[(k2 * 8 + tig + 4) * 68 + nt * 8 + gid];
                #pragma unroll
                for (int mt = 0; mt < 2; mt++)
                    mma_tf32(oAcc[mt][nt], pa[mt][k2], b0, b1);
            }
        }

        __syncthreads();                      // all warps done with stage jt&1
        if (jt + 2 < njt) load_kv(jt + 2, jt & 1);
    }

    // ---- finalize: row sums live across the 4 tig lanes ----
    #pragma unroll
    for (int mt = 0; mt < 2; mt++) {
        #pragma unroll
        for (int o = 1; o < 4; o <<= 1) {
            lsum[mt][0] += __shfl_xor_sync(0xffffffffu, lsum[mt][0], o);
            lsum[mt][1] += __shfl_xor_sync(0xffffffffu, lsum[mt][1], o);
        }
    }

    #pragma unroll
    for (int mt = 0; mt < 2; mt++) {
        float inv0 = 1.f / lsum[mt][0];
        float inv1 = 1.f / lsum[mt][1];
        int r = warp * 32 + mt * 16 + gid;
        #pragma unroll
        for (int nt = 0; nt < 8; nt++) {
            int col = h * 64 + nt * 8 + 2 * tig;
            if (r < ln) {
                uint2 st = make_uint2(f2tf(oAcc[mt][nt][0] * inv0),
                                      f2tf(oAcc[mt][nt][1] * inv0));
                *(uint2*)&Att[(size_t)(b * L_ + start + r) * C_ + col] = st;
            }
            if (r + 8 < ln) {
                uint2 st = make_uint2(f2tf(oAcc[mt][nt][2] * inv1),
                                      f2tf(oAcc[mt][nt][3] * inv1));
                *(uint2*)&Att[(size_t)(b * L_ + start + r + 8) * C_ + col] = st;
            }
        }
    }
}

// ---------------- attention: SMALL segments (0..7, ln<=100) — R12 form ------
__global__ void attn_kernel(const float* __restrict__ Q, const float* __restrict__ Kn,
                            const float* __restrict__ V, const float* __restrict__ sl,
                            float* __restrict__ Att, int seg_hi)
{
    extern __shared__ float smdyn[];
    const int cta = blockIdx.x;
    const int seg = seg_hi - (cta >> 8);
    const int hb  = cta & 255;
    const int h = hb & 15, b = hb >> 4;

    const int pn[10]  = {1, 4, 9, 16, 25, 36, 64, 100, 169, 256};
    const int off[10] = {0, 1, 5, 14, 30, 55, 91, 155, 255, 424};
    const int ln = pn[seg], start = off[seg];

    float* Ks = smdyn;
    float* Vs = smdyn + ln * 64;
    const int tid = threadIdx.x;
    const int nthr4 = blockDim.x * 4;
    const size_t base = ((size_t)(b * H_ + h) * L_ + start) * 64;

    for (int idx = tid * 4; idx < ln * 64; idx += nthr4) {
        *(float4*)&Ks[idx] = *(const float4*)&Kn[base + idx];
        *(float4*)&Vs[idx] = *(const float4*)&V[base + idx];
    }
    const float mfix = expf(fminf(sl[h], MAXLOG));
    __syncthreads();

    u64 op[32];
    float lsum = 0.f;
    if (tid < ln) {
        u64 qp[32];
        const u64* qg = (const u64*)(Q + base + (size_t)tid * 64);
        #pragma unroll
        for (int t = 0; t < 32; t++) { qp[t] = qg[t]; op[t] = 0ull; }

        for (int j = 0; j < ln; j++) {
            const u64* kp = (const u64*)(Ks + j * 64);
            u64 s8[8];
            #pragma unroll
            for (int t = 0; t < 8; t++) s8[t] = 0ull;
            #pragma unroll
            for (int t = 0; t < 32; t++) pfma(s8[t & 7], qp[t], kp[t]);

            float tot = 0.f;
            #pragma unroll
            for (int r = 0; r < 8; r++) { float2 f = up2(s8[r]); tot += f.x + f.y; }

            float p = __expf(tot - mfix);
            lsum += p;
            u64 pp = pk2(p, p);

            const u64* vp = (const u64*)(Vs + j * 64);
            #pragma unroll
            for (int t = 0; t < 32; t++) pfma(op[t], pp, vp[t]);
        }
    }
    __syncthreads();
    if (tid < ln) {
        float inv = 1.0f / lsum;
        #pragma unroll
        for (int t = 0; t < 32; t++) {
            float2 f = up2(op[t]);
            ((unsigned*)Ks)[tid * 64 + 2 * t]     = f2tf(f.x * inv);
            ((unsigned*)Ks)[tid * 64 + 2 * t + 1] = f2tf(f.y * inv);
        }
    }
    __syncthreads();
    const size_t ob = (size_t)(b * L_ + start);
    for (int idx = tid * 4; idx < ln * 64; idx += nthr4) {
        int row = idx >> 6, e = idx & 63;
        *(float4*)&Att[(ob + row) * C_ + h * 64 + e] = *(float4*)&Ks[idx];
    }
}

// ---------------- launch ----------------
extern "C" void kernel_launch(void* const* d_in, const int* in_sizes, int n_in,
                              void* d_out, int out_size)
{
    const float* x    = (const float*)d_in[0];
    // d_in[1] = patch_nums (fixed for this problem; offsets compiled in)
    const float* wqkv = (const float*)d_in[2];
    const float* qb   = (const float*)d_in[3];
    const float* vb   = (const float*)d_in[4];
    const float* slog = (const float*)d_in[5];
    const float* wp   = (const float*)d_in[6];
    const float* pb   = (const float*)d_in[7];
    float* out = (float*)d_out;

    float *qkv, *q, *k, *v, *att, *xr, *wqkvr, *wpr;
    cudaGetSymbolAddress((void**)&qkv,   g_qkv);
    cudaGetSymbolAddress((void**)&q,     g_q);
    cudaGetSymbolAddress((void**)&k,     g_k);
    cudaGetSymbolAddress((void**)&v,     g_v);
    cudaGetSymbolAddress((void**)&att,   g_att);
    cudaGetSymbolAddress((void**)&xr,    g_xr);
    cudaGetSymbolAddress((void**)&wqkvr, g_wqkvr);
    cudaGetSymbolAddress((void**)&wpr,   g_wpr);

    const int attn_small_smem = 2 * 100 * 64 * (int)sizeof(float);  // 51200 B
    cudaFuncSetAttribute(gemm_tf32_kernel,
                         cudaFuncAttributeMaxDynamicSharedMemorySize, GEMM_SMEM);
    cudaFuncSetAttribute(attn_mma_kernel,
                         cudaFuncAttributeMaxDynamicSharedMemorySize, ATT_SMEM);
    cudaFuncSetAttribute(attn_kernel,
                         cudaFuncAttributeMaxDynamicSharedMemorySize, attn_small_smem);

    // 0) pre-round GEMM operands to tf32 (GEMM hot loops are cvt-free)
    {
        const int nx = M_ * C_, nw1 = N1_ * C_, nw2 = C_ * C_;
        round_tf32_kernel<<<nx  / 1024, 256>>>(x,    xr,    nx);
        round_tf32_kernel<<<nw1 / 1024, 256>>>(wqkv, wqkvr, nw1);
        round_tf32_kernel<<<nw2 / 1024, 256>>>(wp,   wpr,   nw2);
    }

    // 1) QKV projection (tf32 mma.sync, 3-stage cp.async, ldmatrix fragments)
    gemm_tf32_kernel<<<dim3(N1_ / 128, M_ / 128), 256, GEMM_SMEM>>>(
        xr, wqkvr, qb, vb, qkv, N1_, C_, 1);

    // 2) l2norm q/k + per-head scale + transpose to [B,H,L,D] (tf32-rounded)
    norm_kernel<<<(M_ * H_) / 8, 256>>>(qkv, slog, q, k, v);

    // 3) attention: big segs 8+9 on tensor cores; small segs on FFMA path
    attn_mma_kernel<<<512, 256, ATT_SMEM>>>(q, k, v, slog, att);
    attn_kernel<<<2048, 128, attn_small_smem>>>(q, k, v, slog, att, 7);

    // 4) output projection (tf32 mma.sync, ldmatrix) -> d_out
    gemm_tf32_kernel<<<dim3(C_ / 128, M_ / 128), 256, GEMM_SMEM>>>(
        att, wpr, pb, nullptr, out, C_, C_, 0);
}

// round 16
// speedup vs baseline: 1.5863x; 1.0558x over previous
#include <cuda_runtime.h>
#include <cstdint>

// Problem constants
#define B_ 16
#define L_ 680
#define C_ 1024
#define H_ 16
#define D_ 64
#define M_ (B_ * L_)     // 10880
#define N1_ (3 * C_)     // 3072
#define MAXLOG 4.605170185988091f   // ln(100)

// ---------------- scratch (static __device__, no allocations) ----------------
__device__ float g_qkv[(size_t)M_ * N1_];          // GEMM1 output [M, 3C]
__device__ float g_q[(size_t)B_ * H_ * L_ * D_];   // normalized q (tf32 bits)
__device__ float g_k[(size_t)B_ * H_ * L_ * D_];   // normalized k (tf32 bits)
__device__ float g_v[(size_t)B_ * H_ * L_ * D_];   // v (tf32 bits)
__device__ float g_att[(size_t)M_ * C_];           // attention out (tf32-rounded)
__device__ float g_xr[(size_t)M_ * C_];            // x rounded to tf32
__device__ float g_wqkvr[(size_t)N1_ * C_];        // wqkv rounded to tf32
__device__ float g_wpr[(size_t)C_ * C_];           // wp rounded to tf32

// ---------------- helpers ----------------
__device__ __forceinline__ unsigned f2tf(float x) {
    unsigned r;
    asm("cvt.rna.tf32.f32 %0, %1;" : "=r"(r) : "f"(x));
    return r;
}
__device__ __forceinline__ float tfr(float x) {     // round to tf32, as float
    return __uint_as_float(f2tf(x));
}

__device__ __forceinline__ void mma_tf32(float c[4], const unsigned a[4],
                                         unsigned b0, unsigned b1) {
    asm volatile(
        "mma.sync.aligned.m16n8k8.row.col.f32.tf32.tf32.f32 "
        "{%0,%1,%2,%3}, {%4,%5,%6,%7}, {%8,%9}, {%0,%1,%2,%3};"
        : "+f"(c[0]), "+f"(c[1]), "+f"(c[2]), "+f"(c[3])
        : "r"(a[0]), "r"(a[1]), "r"(a[2]), "r"(a[3]), "r"(b0), "r"(b1));
}

// ldmatrix: each m8n8.b16 matrix = one 8x4 tile of b32; thread t gets [t>>2][t&3]
__device__ __forceinline__ void ldsm4(unsigned r[4], uint32_t addr) {
    asm volatile("ldmatrix.sync.aligned.m8n8.x4.shared.b16 {%0,%1,%2,%3}, [%4];"
                 : "=r"(r[0]), "=r"(r[1]), "=r"(r[2]), "=r"(r[3]) : "r"(addr));
}
__device__ __forceinline__ void ldsm2(unsigned& r0, unsigned& r1, uint32_t addr) {
    asm volatile("ldmatrix.sync.aligned.m8n8.x2.shared.b16 {%0,%1}, [%2];"
                 : "=r"(r0), "=r"(r1) : "r"(addr));
}

__device__ __forceinline__ void cp16(unsigned* s, const float* g) {
    unsigned sa = (unsigned)__cvta_generic_to_shared(s);
    asm volatile("cp.async.cg.shared.global [%0], [%1], 16;" :: "r"(sa), "l"(g));
}
__device__ __forceinline__ void cp16s(uint32_t s, const float* g) {
    asm volatile("cp.async.cg.shared.global [%0], [%1], 16;" :: "r"(s), "l"(g));
}
__device__ __forceinline__ void cp_commit() {
    asm volatile("cp.async.commit_group;");
}
template<int N> __device__ __forceinline__ void cp_wait() {
    asm volatile("cp.async.wait_group %0;" :: "n"(N));
}

// packed f32x2 primitives — operands STAY packed (no movs in hot loops)
typedef unsigned long long u64;
__device__ __forceinline__ void pfma(u64& d, u64 a, u64 b) {
    asm("fma.rn.f32x2 %0, %1, %2, %0;" : "+l"(d) : "l"(a), "l"(b));
}
__device__ __forceinline__ float2 up2(u64 v) {
    float2 r; asm("mov.b64 {%0, %1}, %2;" : "=f"(r.x), "=f"(r.y) : "l"(v)); return r;
}
__device__ __forceinline__ u64 pk2(float x, float y) {
    u64 r; asm("mov.b64 %0, {%1, %2};" : "=l"(r) : "f"(x), "f"(y)); return r;
}

// ---------------- tf32 pre-round: one launch for x, wqkv, wp ----------------
// Each array's float count is a multiple of 1024, so float4 lanes never
// straddle an array boundary.
__global__ __launch_bounds__(256)
void round3_kernel(const float* __restrict__ x,  float* __restrict__ xr,
                   const float* __restrict__ w1, float* __restrict__ w1r,
                   const float* __restrict__ w2, float* __restrict__ w2r)
{
    const int nx = M_ * C_, nw1 = N1_ * C_;
    int i = (blockIdx.x * 256 + threadIdx.x) * 4;
    const float* s; float* d; int off;
    if (i < nx)            { s = x;  d = xr;  off = i; }
    else if (i < nx + nw1) { s = w1; d = w1r; off = i - nx; }
    else                   { s = w2; d = w2r; off = i - nx - nw1; }
    float4 v = *(const float4*)(s + off);
    uint4 r = make_uint4(f2tf(v.x), f2tf(v.y), f2tf(v.z), f2tf(v.w));
    *(uint4*)(d + off) = r;
}

// ---------------- GEMM: C[m,n] = sum_k A[m,k]*W[n,k] + bias(n) ----------------
// (R14 form: pre-rounded tf32 inputs, 3-stage cp.async, ldmatrix fragments)
#define SROW 36
#define STAGEF (2 * 128 * SROW)
#define GEMM_SMEM (3 * STAGEF * 4)    // 110592 B

__global__ __launch_bounds__(256, 2)
void gemm_tf32_kernel(const float* __restrict__ A, const float* __restrict__ W,
                      const float* __restrict__ b0p, const float* __restrict__ b1p,
                      float* __restrict__ Cout, int N, int K, int mode)
{
    extern __shared__ unsigned sm[];
    const uint32_t smb = (uint32_t)__cvta_generic_to_shared(sm);

    const int bm = blockIdx.y * 128, bn = blockIdx.x * 128;
    const int tid  = threadIdx.x;
    const int lane = tid & 31, warp = tid >> 5;
    const int wm = (warp & 1) * 64;
    const int wn = (warp >> 1) * 32;
    const int gid = lane >> 2, tig = lane & 3;
    const int lrow = tid >> 3;
    const int lcol = (tid & 7) * 4;

    const int a_off = (wm + (lane & 15)) * SROW + (lane >> 4) * 4;
    const int b_off = (wn + (lane & 7))  * SROW + ((lane >> 3) & 1) * 4;

    float acc[4][4][4];
    #pragma unroll
    for (int mt = 0; mt < 4; mt++)
        #pragma unroll
        for (int nt = 0; nt < 4; nt++)
            #pragma unroll
            for (int r = 0; r < 4; r++) acc[mt][nt][r] = 0.f;

    const float* Ag = A + (size_t)(bm + lrow) * K + lcol;
    const float* Wg = W + (size_t)(bn + lrow) * K + lcol;

    const int NCH = K >> 5;

    auto load_chunk = [&](int c, int s) {
        unsigned* sA = sm + s * STAGEF;
        unsigned* sB = sA + 128 * SROW;
        const float* Ap = Ag + (size_t)c * 32;
        const float* Wp = Wg + (size_t)c * 32;
        #pragma unroll
        for (int i = 0; i < 4; i++) {
            cp16(&sA[(lrow + i * 32) * SROW + lcol], Ap + (size_t)i * 32 * K);
            cp16(&sB[(lrow + i * 32) * SROW + lcol], Wp + (size_t)i * 32 * K);
        }
        cp_commit();
    };

    load_chunk(0, 0);
    load_chunk(1, 1);

    int scur = 0;
    for (int it = 0; it < NCH; it++) {
        if (it < NCH - 1) cp_wait<1>(); else cp_wait<0>();
        __syncthreads();

        if (it + 2 < NCH) {
            int snx = scur + 2; if (snx >= 3) snx -= 3;
            load_chunk(it + 2, snx);
        }

        const uint32_t aS = smb + (uint32_t)(scur * STAGEF) * 4u;
        const uint32_t bS = aS + 128u * SROW * 4u;
        const uint32_t aAdr = aS + (uint32_t)a_off * 4u;
        const uint32_t bAdr = bS + (uint32_t)b_off * 4u;

        #pragma unroll
        for (int ks = 0; ks < 32; ks += 8) {
            unsigned a[4][4];
            #pragma unroll
            for (int mt = 0; mt < 4; mt++)
                ldsm4(a[mt], aAdr + (uint32_t)(mt * 16 * SROW + ks) * 4u);
            #pragma unroll
            for (int nt = 0; nt < 4; nt++) {
                unsigned b0, b1;
                ldsm2(b0, b1, bAdr + (uint32_t)(nt * 8 * SROW + ks) * 4u);
                #pragma unroll
                for (int mt = 0; mt < 4; mt++)
                    mma_tf32(acc[mt][nt], a[mt], b0, b1);
            }
        }
        scur = scur + 1; if (scur >= 3) scur = 0;
    }

    #pragma unroll
    for (int mt = 0; mt < 4; mt++) {
        #pragma unroll
        for (int nt = 0; nt < 4; nt++) {
            int row = bm + wm + mt * 16 + gid;
            int col = bn + wn + nt * 8 + 2 * tig;
            float bz0, bz1;
            if (mode == 0) {
                bz0 = b0p[col]; bz1 = b0p[col + 1];
            } else {
                if (col < 1024)       { bz0 = b0p[col];        bz1 = b0p[col + 1]; }
                else if (col < 2048)  { bz0 = 0.f;             bz1 = 0.f; }
                else                  { bz0 = b1p[col - 2048]; bz1 = b1p[col - 2047]; }
            }
            *(float2*)&Cout[(size_t)row * N + col] =
                make_float2(acc[mt][nt][0] + bz0, acc[mt][nt][1] + bz1);
            *(float2*)&Cout[(size_t)(row + 8) * N + col] =
                make_float2(acc[mt][nt][2] + bz0, acc[mt][nt][3] + bz1);
        }
    }
}

// ---------------- l2norm + scale + transpose to [B,H,L,D] ----------------
__global__ __launch_bounds__(256)
void norm_kernel(const float* __restrict__ Y, const float* __restrict__ sl,
                 float* __restrict__ Q, float* __restrict__ Ko, float* __restrict__ V)
{
    int w    = blockIdx.x * 8 + (threadIdx.x >> 5);   // one warp per (m,h)
    int lane = threadIdx.x & 31;
    int m = w >> 4, h = w & 15;
    int b = m / L_, l = m % L_;

    const float* row = Y + (size_t)m * N1_ + h * 64 + lane * 2;
    float2 qv = *(const float2*)(row);
    float2 kv = *(const float2*)(row + 1024);
    float2 vv = *(const float2*)(row + 2048);

    float ssq = qv.x * qv.x + qv.y * qv.y;
    float ssk = kv.x * kv.x + kv.y * kv.y;
    #pragma unroll
    for (int o = 16; o; o >>= 1) {
        ssq += __shfl_xor_sync(0xffffffffu, ssq, o);
        ssk += __shfl_xor_sync(0xffffffffu, ssk, o);
    }
    float qs = expf(fminf(sl[h], MAXLOG)) / fmaxf(sqrtf(ssq), 1e-12f);
    float ks = 1.0f / fmaxf(sqrtf(ssk), 1e-12f);

    size_t ob = ((size_t)(b * H_ + h) * L_ + l) * 64 + lane * 2;
    *(uint2*)(Q  + ob) = make_uint2(f2tf(qv.x * qs), f2tf(qv.y * qs));
    *(uint2*)(Ko + ob) = make_uint2(f2tf(kv.x * ks), f2tf(kv.y * ks));
    *(uint2*)(V  + ob) = make_uint2(f2tf(vv.x),      f2tf(vv.y));
}

// ---------------- merged attention: one launch, 128 threads/CTA -------------
// CTA map (big long-poles first):
//   [   0, 512): seg 9 (ln=256), 2 CTAs per (b,h): half = (cta>>8)&1
//   [ 512,1024): seg 8 (ln=169), 2 CTAs per (b,h)
//   [1024,3072): segs 7..0 FFMA path, seg = 7 - ((cta-1024)>>8)
// Big path: 4 warps, warp = 32 query rows (half*128 + warp*32). K/V tiles of
// 32 keys double-buffered via cp.async. S = Q K^T (m16n8k8 tf32, Q frags in
// regs, K via ldmatrix). Fixed-max softmax (|s|<=scale). P staged per warp in
// smem (tf32-rounded; also summed for lsum so truncation cancels in ratio),
// reloaded via ldmatrix; O += P V. Tail masked (p=0, j>=ln).
// 128 thr * ~200 regs => 2 CTAs/SM (vs 1 for the R15 256-thread version).
// smem words: K stage s @ s*2176 | V @ 4352+s*2176 | P @ 8704+warp*1152
#define ATT_SMEM 53248

__global__ __launch_bounds__(128)
void attn_merged_kernel(const float* __restrict__ Q, const float* __restrict__ Kn,
                        const float* __restrict__ V, const float* __restrict__ sl,
                        float* __restrict__ Att)
{
    extern __shared__ unsigned sm[];
    const uint32_t smb = (uint32_t)__cvta_generic_to_shared(sm);
    const int cta = blockIdx.x;
    const int tid = threadIdx.x;

    if (cta < 1024) {
        // ================= big-segment MMA path =================
        const int is9   = cta < 512;
        const int idx   = cta & 511;
        const int hb    = idx & 255;
        const int half  = idx >> 8;
        const int h = hb & 15, b = hb >> 4;
        const int ln    = is9 ? 256 : 169;
        const int start = is9 ? 424 : 255;

        const int warp = tid >> 5, lane = tid & 31;
        const int gid = lane >> 2, tig = lane & 3;
        const int rbase = half * 128 + warp * 32;

        const size_t base = ((size_t)(b * H_ + h) * L_ + start) * 64;
        const float* Kg = Kn + base;
        const float* Vg = V + base;

        // Q fragments (rows rbase..rbase+31; OOB rows read in-plane, unused)
        unsigned qa[2][8][4];
        {
            const unsigned* Qg = (const unsigned*)(Q + base);
            #pragma unroll
            for (int mt = 0; mt < 2; mt++)
                #pragma unroll
                for (int kt = 0; kt < 8; kt++)
                    #pragma unroll
                    for (int i = 0; i < 4; i++) {
                        int row = rbase + mt * 16 + gid + (i & 1) * 8;
                        int col = kt * 8 + tig + (i >> 1) * 4;
                        qa[mt][kt][i] = Qg[row * 64 + col];
                    }
        }

        float oAcc[2][8][4];
        #pragma unroll
        for (int mt = 0; mt < 2; mt++)
            #pragma unroll
            for (int nt = 0; nt < 8; nt++)
                #pragma unroll
                for (int r = 0; r < 4; r++) oAcc[mt][nt][r] = 0.f;

        float lsum[2][2] = {{0.f, 0.f}, {0.f, 0.f}};
        const float mfix = expf(fminf(sl[h], MAXLOG));
        const int njt = (ln + 31) >> 5;

        auto load_kv = [&](int jt, int s) {
            int j0 = jt * 32;
            #pragma unroll
            for (int i = 0; i < 4; i++) {
                int gr = tid + i * 128;              // 512 granules of 16B
                int r = gr >> 4, c = (gr & 15) * 4;
                uint32_t kd = smb + (uint32_t)(s * 2176 + r * 68 + c) * 4u;
                cp16s(kd,                Kg + (size_t)(j0 + r) * 64 + c);
                cp16s(kd + 4352u * 4u,   Vg + (size_t)(j0 + r) * 64 + c);
            }
            cp_commit();
        };

        load_kv(0, 0);
        load_kv(1, 1);

        const int krow = (lane & 7) + ((lane >> 4) << 3);
        const int kc4  = ((lane >> 3) & 1) << 2;
        const int prow = lane & 15;
        const int pc4  = (lane >> 4) << 2;
        const uint32_t pb = smb + (8704u + (uint32_t)warp * 1152u) * 4u;

        for (int jt = 0; jt < njt; jt++) {
            if (jt + 1 < njt) cp_wait<1>(); else cp_wait<0>();
            __syncthreads();
            const uint32_t ks = smb + (uint32_t)((jt & 1) * 2176) * 4u;
            const unsigned* vs = sm + 4352 + (jt & 1) * 2176;

            // ---- S = Q K^T ----
            float sA[2][4][4];
            #pragma unroll
            for (int mt = 0; mt < 2; mt++)
                #pragma unroll
                for (int nt = 0; nt < 4; nt++)
                    #pragma unroll
                    for (int r = 0; r < 4; r++) sA[mt][nt][r] = 0.f;

            #pragma unroll
            for (int kt = 0; kt < 8; kt++) {
                #pragma unroll
                for (int p = 0; p < 2; p++) {
                    unsigned bb[4];
                    ldsm4(bb, ks + (uint32_t)((p * 16 + krow) * 68 + kt * 8 + kc4) * 4u);
                    #pragma unroll
                    for (int mt = 0; mt < 2; mt++) {
                        mma_tf32(sA[mt][2 * p],     qa[mt][kt], bb[0], bb[1]);
                        mma_tf32(sA[mt][2 * p + 1], qa[mt][kt], bb[2], bb[3]);
                    }
                }
            }

            // ---- exp (fixed max), mask tail, lsum, stage P ----
            float2* P2 = (float2*)(sm + 8704 + warp * 1152);
            #pragma unroll
            for (int mt = 0; mt < 2; mt++)
                #pragma unroll
                for (int nt = 0; nt < 4; nt++) {
                    int jj = jt * 32 + nt * 8 + 2 * tig;
                    float p0 = (jj     < ln) ? tfr(__expf(sA[mt][nt][0] - mfix)) : 0.f;
                    float p1 = (jj + 1 < ln) ? tfr(__expf(sA[mt][nt][1] - mfix)) : 0.f;
                    float p2 = (jj     < ln) ? tfr(__expf(sA[mt][nt][2] - mfix)) : 0.f;
                    float p3 = (jj + 1 < ln) ? tfr(__expf(sA[mt][nt][3] - mfix)) : 0.f;
                    lsum[mt][0] += p0 + p1;
                    lsum[mt][1] += p2 + p3;
                    int w0 = ((mt * 16 + gid) * 36 + nt * 8 + 2 * tig) >> 1;
                    P2[w0]          = make_float2(p0, p1);
                    P2[w0 + 4 * 36] = make_float2(p2, p3);   // +8 rows
                }
            __syncwarp();

            // ---- reload P as A fragments ----
            unsigned pa[2][4][4];
            #pragma unroll
            for (int mt = 0; mt < 2; mt++)
                #pragma unroll
                for (int k2 = 0; k2 < 4; k2++)
                    ldsm4(pa[mt][k2],
                          pb + (uint32_t)((mt * 16 + prow) * 36 + k2 * 8 + pc4) * 4u);

            // ---- O += P V ----
            #pragma unroll
            for (int k2 = 0; k2 < 4; k2++) {
                #pragma unroll
                for (int nt = 0; nt < 8; nt++) {
                    unsigned b0 = vs[(k2 * 8 + tig)     * 68 + nt * 8 + gid];
                    unsigned b1 = vs[(k2 * 8 + tig + 4) * 68 + nt * 8 + gid];
                    #pragma unroll
                    for (int mt = 0; mt < 2; mt++)
                        mma_tf32(oAcc[mt][nt], pa[mt][k2], b0, b1);
                }
            }

            __syncthreads();
            if (jt + 2 < njt) load_kv(jt + 2, jt & 1);
        }

        // ---- finalize ----
        #pragma unroll
        for (int mt = 0; mt < 2; mt++) {
            #pragma unroll
            for (int o = 1; o < 4; o <<= 1) {
                lsum[mt][0] += __shfl_xor_sync(0xffffffffu, lsum[mt][0], o);
                lsum[mt][1] += __shfl_xor_sync(0xffffffffu, lsum[mt][1], o);
            }
        }
        #pragma unroll
        for (int mt = 0; mt < 2; mt++) {
            float inv0 = 1.f / lsum[mt][0];
            float inv1 = 1.f / lsum[mt][1];
            int r = rbase + mt * 16 + gid;
            #pragma unroll
            for (int nt = 0; nt < 8; nt++) {
                int col = h * 64 + nt * 8 + 2 * tig;
                if (r < ln) {
                    uint2 st = make_uint2(f2tf(oAcc[mt][nt][0] * inv0),
                                          f2tf(oAcc[mt][nt][1] * inv0));
                    *(uint2*)&Att[(size_t)(b * L_ + start + r) * C_ + col] = st;
                }
                if (r + 8 < ln) {
                    uint2 st = make_uint2(f2tf(oAcc[mt][nt][2] * inv1),
                                          f2tf(oAcc[mt][nt][3] * inv1));
                    *(uint2*)&Att[(size_t)(b * L_ + start + r + 8) * C_ + col] = st;
                }
            }
        }
    } else {
        // ================= small-segment FFMA path (R12 form) =================
        float* smf = (float*)sm;
        const int idx = cta - 1024;
        const int seg = 7 - (idx >> 8);
        const int hb  = idx & 255;
        const int h = hb & 15, b = hb >> 4;

        const int pn[8]  = {1, 4, 9, 16, 25, 36, 64, 100};
        const int off[8] = {0, 1, 5, 14, 30, 55, 91, 155};
        const int ln = pn[seg], start = off[seg];

        float* Ks = smf;
        float* Vs = smf + ln * 64;
        const size_t base = ((size_t)(b * H_ + h) * L_ + start) * 64;

        for (int i2 = tid * 4; i2 < ln * 64; i2 += 512) {
            *(float4*)&Ks[i2] = *(const float4*)&Kn[base + i2];
            *(float4*)&Vs[i2] = *(const float4*)&V[base + i2];
        }
        const float mfix = expf(fminf(sl[h], MAXLOG));
        __syncthreads();

        u64 op[32];
        float lsum = 0.f;
        if (tid < ln) {
            u64 qp[32];
            const u64* qg = (const u64*)(Q + base + (size_t)tid * 64);
            #pragma unroll
            for (int t = 0; t < 32; t++) { qp[t] = qg[t]; op[t] = 0ull; }

            for (int j = 0; j < ln; j++) {
                const u64* kp = (const u64*)(Ks + j * 64);
                u64 s8[8];
                #pragma unroll
                for (int t = 0; t < 8; t++) s8[t] = 0ull;
                #pragma unroll
                for (int t = 0; t < 32; t++) pfma(s8[t & 7], qp[t], kp[t]);

                float tot = 0.f;
                #pragma unroll
                for (int r = 0; r < 8; r++) { float2 f = up2(s8[r]); tot += f.x + f.y; }

                float p = __expf(tot - mfix);
                lsum += p;
                u64 pp = pk2(p, p);

                const u64* vp = (const u64*)(Vs + j * 64);
                #pragma unroll
                for (int t = 0; t < 32; t++) pfma(op[t], pp, vp[t]);
            }
        }
        __syncthreads();
        if (tid < ln) {
            float inv = 1.0f / lsum;
            #pragma unroll
            for (int t = 0; t < 32; t++) {
                float2 f = up2(op[t]);
                ((unsigned*)Ks)[tid * 64 + 2 * t]     = f2tf(f.x * inv);
                ((unsigned*)Ks)[tid * 64 + 2 * t + 1] = f2tf(f.y * inv);
            }
        }
        __syncthreads();
        const size_t ob = (size_t)(b * L_ + start);
        for (int i2 = tid * 4; i2 < ln * 64; i2 += 512) {
            int row = i2 >> 6, e = i2 & 63;
            *(float4*)&Att[(ob + row) * C_ + h * 64 + e] = *(float4*)&Ks[i2];
        }
    }
}

// ---------------- launch ----------------
extern "C" void kernel_launch(void* const* d_in, const int* in_sizes, int n_in,
                              void* d_out, int out_size)
{
    const float* x    = (const float*)d_in[0];
    // d_in[1] = patch_nums (fixed for this problem; offsets compiled in)
    const float* wqkv = (const float*)d_in[2];
    const float* qb   = (const float*)d_in[3];
    const float* vb   = (const float*)d_in[4];
    const float* slog = (const float*)d_in[5];
    const float* wp   = (const float*)d_in[6];
    const float* pb   = (const float*)d_in[7];
    float* out = (float*)d_out;

    float *qkv, *q, *k, *v, *att, *xr, *wqkvr, *wpr;
    cudaGetSymbolAddress((void**)&qkv,   g_qkv);
    cudaGetSymbolAddress((void**)&q,     g_q);
    cudaGetSymbolAddress((void**)&k,     g_k);
    cudaGetSymbolAddress((void**)&v,     g_v);
    cudaGetSymbolAddress((void**)&att,   g_att);
    cudaGetSymbolAddress((void**)&xr,    g_xr);
    cudaGetSymbolAddress((void**)&wqkvr, g_wqkvr);
    cudaGetSymbolAddress((void**)&wpr,   g_wpr);

    cudaFuncSetAttribute(gemm_tf32_kernel,
                         cudaFuncAttributeMaxDynamicSharedMemorySize, GEMM_SMEM);
    cudaFuncSetAttribute(attn_merged_kernel,
                         cudaFuncAttributeMaxDynamicSharedMemorySize, ATT_SMEM);

    // 0) pre-round all GEMM operands to tf32 in ONE launch
    {
        const int ntot = M_ * C_ + N1_ * C_ + C_ * C_;   // 15,335,424
        round3_kernel<<<ntot / 1024, 256>>>(x, xr, wqkv, wqkvr, wp, wpr);
    }

    // 1) QKV projection (tf32 mma.sync, 3-stage cp.async, ldmatrix fragments)
    gemm_tf32_kernel<<<dim3(N1_ / 128, M_ / 128), 256, GEMM_SMEM>>>(
        xr, wqkvr, qb, vb, qkv, N1_, C_, 1);

    // 2) l2norm q/k + per-head scale + transpose to [B,H,L,D] (tf32-rounded)
    norm_kernel<<<(M_ * H_) / 8, 256>>>(qkv, slog, q, k, v);

    // 3) ALL attention in one launch: big segs (MMA, 2 CTAs/SM) first,
    //    small segs (FFMA) backfill
    attn_merged_kernel<<<3072, 128, ATT_SMEM>>>(q, k, v, slog, att);

    // 4) output projection (tf32 mma.sync, ldmatrix) -> d_out
    gemm_tf32_kernel<<<dim3(C_ / 128, M_ / 128), 256, GEMM_SMEM>>>(
        att, wpr, pb, nullptr, out, C_, C_, 0);
}

// round 17
// speedup vs baseline: 1.6150x; 1.0181x over previous
#include <cuda_runtime.h>
#include <cstdint>

// Problem constants
#define B_ 16
#define L_ 680
#define C_ 1024
#define H_ 16
#define D_ 64
#define M_ (B_ * L_)     // 10880
#define N1_ (3 * C_)     // 3072
#define MAXLOG 4.605170185988091f   // ln(100)

// ---------------- scratch (static __device__, no allocations) ----------------
__device__ float g_q[(size_t)B_ * H_ * L_ * D_];   // normalized q (tf32 bits)
__device__ float g_k[(size_t)B_ * H_ * L_ * D_];   // normalized k (tf32 bits)
__device__ float g_v[(size_t)B_ * H_ * L_ * D_];   // v (tf32 bits)
__device__ float g_att[(size_t)M_ * C_];           // attention out (tf32-rounded)
__device__ float g_xr[(size_t)M_ * C_];            // x rounded to tf32
__device__ float g_wqkvr[(size_t)N1_ * C_];        // wqkv rounded to tf32
__device__ float g_wpr[(size_t)C_ * C_];           // wp rounded to tf32

// ---------------- helpers ----------------
__device__ __forceinline__ unsigned f2tf(float x) {
    unsigned r;
    asm("cvt.rna.tf32.f32 %0, %1;" : "=r"(r) : "f"(x));
    return r;
}
__device__ __forceinline__ float tfr(float x) {     // round to tf32, as float
    return __uint_as_float(f2tf(x));
}

__device__ __forceinline__ void mma_tf32(float c[4], const unsigned a[4],
                                         unsigned b0, unsigned b1) {
    asm volatile(
        "mma.sync.aligned.m16n8k8.row.col.f32.tf32.tf32.f32 "
        "{%0,%1,%2,%3}, {%4,%5,%6,%7}, {%8,%9}, {%0,%1,%2,%3};"
        : "+f"(c[0]), "+f"(c[1]), "+f"(c[2]), "+f"(c[3])
        : "r"(a[0]), "r"(a[1]), "r"(a[2]), "r"(a[3]), "r"(b0), "r"(b1));
}

// ldmatrix: each m8n8.b16 matrix = one 8x4 tile of b32; thread t gets [t>>2][t&3]
__device__ __forceinline__ void ldsm4(unsigned r[4], uint32_t addr) {
    asm volatile("ldmatrix.sync.aligned.m8n8.x4.shared.b16 {%0,%1,%2,%3}, [%4];"
                 : "=r"(r[0]), "=r"(r[1]), "=r"(r[2]), "=r"(r[3]) : "r"(addr));
}

__device__ __forceinline__ void cp16(unsigned* s, const float* g) {
    unsigned sa = (unsigned)__cvta_generic_to_shared(s);
    asm volatile("cp.async.cg.shared.global [%0], [%1], 16;" :: "r"(sa), "l"(g));
}
__device__ __forceinline__ void cp16s(uint32_t s, const float* g) {
    asm volatile("cp.async.cg.shared.global [%0], [%1], 16;" :: "r"(s), "l"(g));
}
__device__ __forceinline__ void cp_commit() {
    asm volatile("cp.async.commit_group;");
}
template<int N> __device__ __forceinline__ void cp_wait() {
    asm volatile("cp.async.wait_group %0;" :: "n"(N));
}

// packed f32x2 primitives — operands STAY packed (no movs in hot loops)
typedef unsigned long long u64;
__device__ __forceinline__ void pfma(u64& d, u64 a, u64 b) {
    asm("fma.rn.f32x2 %0, %1, %2, %0;" : "+l"(d) : "l"(a), "l"(b));
}
__device__ __forceinline__ float2 up2(u64 v) {
    float2 r; asm("mov.b64 {%0, %1}, %2;" : "=f"(r.x), "=f"(r.y) : "l"(v)); return r;
}
__device__ __forceinline__ u64 pk2(float x, float y) {
    u64 r; asm("mov.b64 %0, {%1, %2};" : "=l"(r) : "f"(x), "f"(y)); return r;
}

// ---------------- tf32 pre-round: one launch for x, wqkv, wp ----------------
__global__ __launch_bounds__(256)
void round3_kernel(const float* __restrict__ x,  float* __restrict__ xr,
                   const float* __restrict__ w1, float* __restrict__ w1r,
                   const float* __restrict__ w2, float* __restrict__ w2r)
{
    const int nx = M_ * C_, nw1 = N1_ * C_;
    int i = (blockIdx.x * 256 + threadIdx.x) * 4;
    const float* s; float* d; int off;
    if (i < nx)            { s = x;  d = xr;  off = i; }
    else if (i < nx + nw1) { s = w1; d = w1r; off = i - nx; }
    else                   { s = w2; d = w2r; off = i - nx - nw1; }
    float4 v = *(const float4*)(s + off);
    uint4 r = make_uint4(f2tf(v.x), f2tf(v.y), f2tf(v.z), f2tf(v.w));
    *(uint4*)(d + off) = r;
}

// ---------------- GEMM: C[m,n] = sum_k A[m,k]*W[n,k] + bias(n) ----------------
// Pre-rounded tf32 inputs; 3-stage cp.async; ldmatrix fragments (A x4, B x4
// covering nt pairs). mode 0: plain epilogue, bias=b0p -> Cout.
// mode 1 (QKV): FUSED epilogue — stage acc+bias to smem tile, per-(row,head)
// l2norm/scale (identical formulas to the old norm kernel), write tf32-rounded
// direct to Qo/Ko/Vo in [B,H,L,D]. The 128-col tile = exactly 2 heads.
#define SROW 36
#define STAGEF (2 * 128 * SROW)
#define GEMM_SMEM (3 * STAGEF * 4)    // 110592 B

__global__ __launch_bounds__(256, 2)
void gemm_tf32_kernel(const float* __restrict__ A, const float* __restrict__ W,
                      const float* __restrict__ b0p, const float* __restrict__ b1p,
                      float* __restrict__ Cout, int N, int K, int mode,
                      const float* __restrict__ slog,
                      float* __restrict__ Qo, float* __restrict__ Ko,
                      float* __restrict__ Vo)
{
    extern __shared__ unsigned sm[];
    const uint32_t smb = (uint32_t)__cvta_generic_to_shared(sm);

    const int bm = blockIdx.y * 128, bn = blockIdx.x * 128;
    const int tid  = threadIdx.x;
    const int lane = tid & 31, warp = tid >> 5;
    const int wm = (warp & 1) * 64;
    const int wn = (warp >> 1) * 32;
    const int gid = lane >> 2, tig = lane & 3;
    const int lrow = tid >> 3;
    const int lcol = (tid & 7) * 4;

    const int a_off = (wm + (lane & 15)) * SROW + (lane >> 4) * 4;
    const int b_off = (wn + ((lane >> 4) << 3) + (lane & 7)) * SROW
                    + ((lane >> 3) & 1) * 4;

    float acc[4][4][4];
    #pragma unroll
    for (int mt = 0; mt < 4; mt++)
        #pragma unroll
        for (int nt = 0; nt < 4; nt++)
            #pragma unroll
            for (int r = 0; r < 4; r++) acc[mt][nt][r] = 0.f;

    const float* Ag = A + (size_t)(bm + lrow) * K + lcol;
    const float* Wg = W + (size_t)(bn + lrow) * K + lcol;

    const int NCH = K >> 5;

    auto load_chunk = [&](int c, int s) {
        unsigned* sA = sm + s * STAGEF;
        unsigned* sB = sA + 128 * SROW;
        const float* Ap = Ag + (size_t)c * 32;
        const float* Wp = Wg + (size_t)c * 32;
        #pragma unroll
        for (int i = 0; i < 4; i++) {
            cp16(&sA[(lrow + i * 32) * SROW + lcol], Ap + (size_t)i * 32 * K);
            cp16(&sB[(lrow + i * 32) * SROW + lcol], Wp + (size_t)i * 32 * K);
        }
        cp_commit();
    };

    load_chunk(0, 0);
    load_chunk(1, 1);

    int scur = 0;
    for (int it = 0; it < NCH; it++) {
        if (it < NCH - 1) cp_wait<1>(); else cp_wait<0>();
        __syncthreads();

        if (it + 2 < NCH) {
            int snx = scur + 2; if (snx >= 3) snx -= 3;
            load_chunk(it + 2, snx);
        }

        const uint32_t aS = smb + (uint32_t)(scur * STAGEF) * 4u;
        const uint32_t aAdr = aS + (uint32_t)a_off * 4u;
        const uint32_t bAdr = aS + 128u * SROW * 4u + (uint32_t)b_off * 4u;

        #pragma unroll
        for (int ks = 0; ks < 32; ks += 8) {
            unsigned a[4][4];
            #pragma unroll
            for (int mt = 0; mt < 4; mt++)
                ldsm4(a[mt], aAdr + (uint32_t)(mt * 16 * SROW + ks) * 4u);
            #pragma unroll
            for (int ntp = 0; ntp < 2; ntp++) {
                unsigned bb[4];
                ldsm4(bb, bAdr + (uint32_t)(ntp * 16 * SROW + ks) * 4u);
                #pragma unroll
                for (int mt = 0; mt < 4; mt++) {
                    mma_tf32(acc[mt][2 * ntp],     a[mt], bb[0], bb[1]);
                    mma_tf32(acc[mt][2 * ntp + 1], a[mt], bb[2], bb[3]);
                }
            }
        }
        scur = scur + 1; if (scur >= 3) scur = 0;
    }

    if (mode == 0) {
        // -------- plain epilogue: bias + store to Cout --------
        #pragma unroll
        for (int mt = 0; mt < 4; mt++) {
            #pragma unroll
            for (int nt = 0; nt < 4; nt++) {
                int row = bm + wm + mt * 16 + gid;
                int col = bn + wn + nt * 8 + 2 * tig;
                float bz0 = b0p[col], bz1 = b0p[col + 1];
                *(float2*)&Cout[(size_t)row * N + col] =
                    make_float2(acc[mt][nt][0] + bz0, acc[mt][nt][1] + bz1);
                *(float2*)&Cout[(size_t)(row + 8) * N + col] =
                    make_float2(acc[mt][nt][2] + bz0, acc[mt][nt][3] + bz1);
            }
        }
    } else {
        // -------- fused QKV epilogue: bias -> smem tile -> norm -> [B,H,L,D] --------
        __syncthreads();                       // mainloop reads of smem done
        float* tile = (float*)sm;              // 128 x 132 fp32 (67.6 KB)
        #pragma unroll
        for (int mt = 0; mt < 4; mt++) {
            #pragma unroll
            for (int nt = 0; nt < 4; nt++) {
                int r0 = wm + mt * 16 + gid;
                int c  = wn + nt * 8 + 2 * tig;
                int col = bn + c;
                float bz0, bz1;
                if (col < 1024)       { bz0 = b0p[col];        bz1 = b0p[col + 1]; }
                else if (col < 2048)  { bz0 = 0.f;             bz1 = 0.f; }
                else                  { bz0 = b1p[col - 2048]; bz1 = b1p[col - 2047]; }
                *(float2*)&tile[r0 * 132 + c] =
                    make_float2(acc[mt][nt][0] + bz0, acc[mt][nt][1] + bz1);
                *(float2*)&tile[(r0 + 8) * 132 + c] =
                    make_float2(acc[mt][nt][2] + bz0, acc[mt][nt][3] + bz1);
            }
        }
        __syncthreads();

        const int kind = bn >> 10;             // 0=q, 1=k, 2=v
        const int h0 = (bn & 1023) >> 6;
        float* dst = (kind == 0) ? Qo : ((kind == 1) ? Ko : Vo);

        for (int pi = warp; pi < 256; pi += 8) {   // one warp per (row, head)
            int row = pi >> 1, hh = pi & 1;
            int m = bm + row;
            int b = m / L_, l = m - b * L_;
            int h = h0 + hh;
            float2 vv = *(float2*)&tile[row * 132 + hh * 64 + lane * 2];
            float s = 1.f;
            if (kind == 0) {
                float ss = vv.x * vv.x + vv.y * vv.y;
                #pragma unroll
                for (int o = 16; o; o >>= 1) ss += __shfl_xor_sync(0xffffffffu, ss, o);
                s = expf(fminf(slog[h], MAXLOG)) / fmaxf(sqrtf(ss), 1e-12f);
            } else if (kind == 1) {
                float ss = vv.x * vv.x + vv.y * vv.y;
                #pragma unroll
                for (int o = 16; o; o >>= 1) ss += __shfl_xor_sync(0xffffffffu, ss, o);
                s = 1.f / fmaxf(sqrtf(ss), 1e-12f);
            }
            size_t ob = ((size_t)(b * H_ + h) * L_ + l) * 64 + lane * 2;
            *(uint2*)&dst[ob] = make_uint2(f2tf(vv.x * s), f2tf(vv.y * s));
        }
    }
}

// ---------------- merged attention: one launch, 128 threads/CTA -------------
// CTA map (big long-poles first):
//   [   0, 512): seg 9 (ln=256), 2 CTAs per (b,h): half = (cta>>8)&1
//   [ 512,1024): seg 8 (ln=169), 2 CTAs per (b,h)
//   [1024,3072): segs 7..0 FFMA path, seg = 7 - ((cta-1024)>>8)
#define ATT_SMEM 53248

__global__ __launch_bounds__(128)
void attn_merged_kernel(const float* __restrict__ Q, const float* __restrict__ Kn,
                        const float* __restrict__ V, const float* __restrict__ sl,
                        float* __restrict__ Att)
{
    extern __shared__ unsigned sm[];
    const uint32_t smb = (uint32_t)__cvta_generic_to_shared(sm);
    const int cta = blockIdx.x;
    const int tid = threadIdx.x;

    if (cta < 1024) {
        // ================= big-segment MMA path =================
        const int is9   = cta < 512;
        const int idx   = cta & 511;
        const int hb    = idx & 255;
        const int half  = idx >> 8;
        const int h = hb & 15, b = hb >> 4;
        const int ln    = is9 ? 256 : 169;
        const int start = is9 ? 424 : 255;

        const int warp = tid >> 5, lane = tid & 31;
        const int gid = lane >> 2, tig = lane & 3;
        const int rbase = half * 128 + warp * 32;

        const size_t base = ((size_t)(b * H_ + h) * L_ + start) * 64;
        const float* Kg = Kn + base;
        const float* Vg = V + base;

        unsigned qa[2][8][4];
        {
            const unsigned* Qg = (const unsigned*)(Q + base);
            #pragma unroll
            for (int mt = 0; mt < 2; mt++)
                #pragma unroll
                for (int kt = 0; kt < 8; kt++)
                    #pragma unroll
                    for (int i = 0; i < 4; i++) {
                        int row = rbase + mt * 16 + gid + (i & 1) * 8;
                        int col = kt * 8 + tig + (i >> 1) * 4;
                        qa[mt][kt][i] = Qg[row * 64 + col];
                    }
        }

        float oAcc[2][8][4];
        #pragma unroll
        for (int mt = 0; mt < 2; mt++)
            #pragma unroll
            for (int nt = 0; nt < 8; nt++)
                #pragma unroll
                for (int r = 0; r < 4; r++) oAcc[mt][nt][r] = 0.f;

        float lsum[2][2] = {{0.f, 0.f}, {0.f, 0.f}};
        const float mfix = expf(fminf(sl[h], MAXLOG));
        const int njt = (ln + 31) >> 5;

        auto load_kv = [&](int jt, int s) {
            int j0 = jt * 32;
            #pragma unroll
            for (int i = 0; i < 4; i++) {
                int gr = tid + i * 128;
                int r = gr >> 4, c = (gr & 15) * 4;
                uint32_t kd = smb + (uint32_t)(s * 2176 + r * 68 + c) * 4u;
                cp16s(kd,              Kg + (size_t)(j0 + r) * 64 + c);
                cp16s(kd + 4352u * 4u, Vg + (size_t)(j0 + r) * 64 + c);
            }
            cp_commit();
        };

        load_kv(0, 0);
        load_kv(1, 1);

        const int krow = (lane & 7) + ((lane >> 4) << 3);
        const int kc4  = ((lane >> 3) & 1) << 2;
        const int prow = lane & 15;
        const int pc4  = (lane >> 4) << 2;
        const uint32_t pb = smb + (8704u + (uint32_t)warp * 1152u) * 4u;

        for (int jt = 0; jt < njt; jt++) {
            if (jt + 1 < njt) cp_wait<1>(); else cp_wait<0>();
            __syncthreads();
            const uint32_t ks = smb + (uint32_t)((jt & 1) * 2176) * 4u;
            const unsigned* vs = sm + 4352 + (jt & 1) * 2176;

            float sA[2][4][4];
            #pragma unroll
            for (int mt = 0; mt < 2; mt++)
                #pragma unroll
                for (int nt = 0; nt < 4; nt++)
                    #pragma unroll
                    for (int r = 0; r < 4; r++) sA[mt][nt][r] = 0.f;

            #pragma unroll
            for (int kt = 0; kt < 8; kt++) {
                #pragma unroll
                for (int p = 0; p < 2; p++) {
                    unsigned bb[4];
                    ldsm4(bb, ks + (uint32_t)((p * 16 + krow) * 68 + kt * 8 + kc4) * 4u);
                    #pragma unroll
                    for (int mt = 0; mt < 2; mt++) {
                        mma_tf32(sA[mt][2 * p],     qa[mt][kt], bb[0], bb[1]);
                        mma_tf32(sA[mt][2 * p + 1], qa[mt][kt], bb[2], bb[3]);
                    }
                }
            }

            float2* P2 = (float2*)(sm + 8704 + warp * 1152);
            #pragma unroll
            for (int mt = 0; mt < 2; mt++)
                #pragma unroll
                for (int nt = 0; nt < 4; nt++) {
                    int jj = jt * 32 + nt * 8 + 2 * tig;
                    float p0 = (jj     < ln) ? tfr(__expf(sA[mt][nt][0] - mfix)) : 0.f;
                    float p1 = (jj + 1 < ln) ? tfr(__expf(sA[mt][nt][1] - mfix)) : 0.f;
                    float p2 = (jj     < ln) ? tfr(__expf(sA[mt][nt][2] - mfix)) : 0.f;
                    float p3 = (jj + 1 < ln) ? tfr(__expf(sA[mt][nt][3] - mfix)) : 0.f;
                    lsum[mt][0] += p0 + p1;
                    lsum[mt][1] += p2 + p3;
                    int w0 = ((mt * 16 + gid) * 36 + nt * 8 + 2 * tig) >> 1;
                    P2[w0]          = make_float2(p0, p1);
                    P2[w0 + 4 * 36] = make_float2(p2, p3);
                }
            __syncwarp();

            unsigned pa[2][4][4];
            #pragma unroll
            for (int mt = 0; mt < 2; mt++)
                #pragma unroll
                for (int k2 = 0; k2 < 4; k2++)
                    ldsm4(pa[mt][k2],
                          pb + (uint32_t)((mt * 16 + prow) * 36 + k2 * 8 + pc4) * 4u);

            #pragma unroll
            for (int k2 = 0; k2 < 4; k2++) {
                #pragma unroll
                for (int nt = 0; nt < 8; nt++) {
                    unsigned b0 = vs[(k2 * 8 + tig)     * 68 + nt * 8 + gid];
                    unsigned b1 = vs[(k2 * 8 + tig + 4) * 68 + nt * 8 + gid];
                    #pragma unroll
                    for (int mt = 0; mt < 2; mt++)
                        mma_tf32(oAcc[mt][nt], pa[mt][k2], b0, b1);
                }
            }

            __syncthreads();
            if (jt + 2 < njt) load_kv(jt + 2, jt & 1);
        }

        #pragma unroll
        for (int mt = 0; mt < 2; mt++) {
            #pragma unroll
            for (int o = 1; o < 4; o <<= 1) {
                lsum[mt][0] += __shfl_xor_sync(0xffffffffu, lsum[mt][0], o);
                lsum[mt][1] += __shfl_xor_sync(0xffffffffu, lsum[mt][1], o);
            }
        }
        #pragma unroll
        for (int mt = 0; mt < 2; mt++) {
            float inv0 = 1.f / lsum[mt][0];
            float inv1 = 1.f / lsum[mt][1];
            int r = rbase + mt * 16 + gid;
            #pragma unroll
            for (int nt = 0; nt < 8; nt++) {
                int col = h * 64 + nt * 8 + 2 * tig;
                if (r < ln) {
                    uint2 st = make_uint2(f2tf(oAcc[mt][nt][0] * inv0),
                                          f2tf(oAcc[mt][nt][1] * inv0));
                    *(uint2*)&Att[(size_t)(b * L_ + start + r) * C_ + col] = st;
                }
                if (r + 8 < ln) {
                    uint2 st = make_uint2(f2tf(oAcc[mt][nt][2] * inv1),
                                          f2tf(oAcc[mt][nt][3] * inv1));
                    *(uint2*)&Att[(size_t)(b * L_ + start + r + 8) * C_ + col] = st;
                }
            }
        }
    } else {
        // ================= small-segment FFMA path (R12 form) =================
        float* smf = (float*)sm;
        const int idx = cta - 1024;
        const int seg = 7 - (idx >> 8);
        const int hb  = idx & 255;
        const int h = hb & 15, b = hb >> 4;

        const int pn[8]  = {1, 4, 9, 16, 25, 36, 64, 100};
        const int off[8] = {0, 1, 5, 14, 30, 55, 91, 155};
        const int ln = pn[seg], start = off[seg];

        float* Ks = smf;
        float* Vs = smf + ln * 64;
        const size_t base = ((size_t)(b * H_ + h) * L_ + start) * 64;

        for (int i2 = tid * 4; i2 < ln * 64; i2 += 512) {
            *(float4*)&Ks[i2] = *(const float4*)&Kn[base + i2];
            *(float4*)&Vs[i2] = *(const float4*)&V[base + i2];
        }
        const float mfix = expf(fminf(sl[h], MAXLOG));
        __syncthreads();

        u64 op[32];
        float lsum = 0.f;
        if (tid < ln) {
            u64 qp[32];
            const u64* qg = (const u64*)(Q + base + (size_t)tid * 64);
            #pragma unroll
            for (int t = 0; t < 32; t++) { qp[t] = qg[t]; op[t] = 0ull; }

            for (int j = 0; j < ln; j++) {
                const u64* kp = (const u64*)(Ks + j * 64);
                u64 s8[8];
                #pragma unroll
                for (int t = 0; t < 8; t++) s8[t] = 0ull;
                #pragma unroll
                for (int t = 0; t < 32; t++) pfma(s8[t & 7], qp[t], kp[t]);

                float tot = 0.f;
                #pragma unroll
                for (int r = 0; r < 8; r++) { float2 f = up2(s8[r]); tot += f.x + f.y; }

                float p = __expf(tot - mfix);
                lsum += p;
                u64 pp = pk2(p, p);

                const u64* vp = (const u64*)(Vs + j * 64);
                #pragma unroll
                for (int t = 0; t < 32; t++) pfma(op[t], pp, vp[t]);
            }
        }
        __syncthreads();
        if (tid < ln) {
            float inv = 1.0f / lsum;
            #pragma unroll
            for (int t = 0; t < 32; t++) {
                float2 f = up2(op[t]);
                ((unsigned*)Ks)[tid * 64 + 2 * t]     = f2tf(f.x * inv);
                ((unsigned*)Ks)[tid * 64 + 2 * t + 1] = f2tf(f.y * inv);
            }
        }
        __syncthreads();
        const size_t ob = (size_t)(b * L_ + start);
        for (int i2 = tid * 4; i2 < ln * 64; i2 += 512) {
            int row = i2 >> 6, e = i2 & 63;
            *(float4*)&Att[(ob + row) * C_ + h * 64 + e] = *(float4*)&Ks[i2];
        }
    }
}

// ---------------- launch ----------------
extern "C" void kernel_launch(void* const* d_in, const int* in_sizes, int n_in,
                              void* d_out, int out_size)
{
    const float* x    = (const float*)d_in[0];
    // d_in[1] = patch_nums (fixed for this problem; offsets compiled in)
    const float* wqkv = (const float*)d_in[2];
    const float* qb   = (const float*)d_in[3];
    const float* vb   = (const float*)d_in[4];
    const float* slog = (const float*)d_in[5];
    const float* wp   = (const float*)d_in[6];
    const float* pb   = (const float*)d_in[7];
    float* out = (float*)d_out;

    float *q, *k, *v, *att, *xr, *wqkvr, *wpr;
    cudaGetSymbolAddress((void**)&q,     g_q);
    cudaGetSymbolAddress((void**)&k,     g_k);
    cudaGetSymbolAddress((void**)&v,     g_v);
    cudaGetSymbolAddress((void**)&att,   g_att);
    cudaGetSymbolAddress((void**)&xr,    g_xr);
    cudaGetSymbolAddress((void**)&wqkvr, g_wqkvr);
    cudaGetSymbolAddress((void**)&wpr,   g_wpr);

    cudaFuncSetAttribute(gemm_tf32_kernel,
                         cudaFuncAttributeMaxDynamicSharedMemorySize, GEMM_SMEM);
    cudaFuncSetAttribute(attn_merged_kernel,
                         cudaFuncAttributeMaxDynamicSharedMemorySize, ATT_SMEM);

    // 0) pre-round all GEMM operands to tf32 in ONE launch
    {
        const int ntot = M_ * C_ + N1_ * C_ + C_ * C_;   // 15,335,424
        round3_kernel<<<ntot / 1024, 256>>>(x, xr, wqkv, wqkvr, wp, wpr);
    }

    // 1) QKV projection with FUSED l2norm/scale/transpose epilogue ->
    //    writes g_q/g_k/g_v directly (no qkv buffer, no norm kernel)
    gemm_tf32_kernel<<<dim3(N1_ / 128, M_ / 128), 256, GEMM_SMEM>>>(
        xr, wqkvr, qb, vb, nullptr, N1_, C_, 1, slog, q, k, v);

    // 2) ALL attention in one launch: big segs (MMA) first, small segs backfill
    attn_merged_kernel<<<3072, 128, ATT_SMEM>>>(q, k, v, slog, att);

    // 3) output projection (tf32 mma.sync, ldmatrix) -> d_out
    gemm_tf32_kernel<<<dim3(C_ / 128, M_ / 128), 256, GEMM_SMEM>>>(
        att, wpr, pb, nullptr, out, C_, C_, 0, nullptr, nullptr, nullptr, nullptr);
}